// round 10
// baseline (speedup 1.0000x reference)
#include <cuda_runtime.h>
#include <math.h>

#define MM    2049        // mesh points
#define NK    1025        // kappa = 0..1024 (Hermitian half)
#define NPAD  1152        // padded m-pair count (9 chunks of 128)
#define NB    16          // batch
#define NPT   1024        // points per batch
#define NJ    32          // (b,c) pairs: j = b*2 + c

// ---- f32-faithful constants ----
#define C2PL_F   ((float)(2.0 * M_PI / 10.0))          // 2*pi/L as f32
#define FT32_F   ((float)(4.0 * 2.821e-5))             // 4*tau as f32
#define WIN_R    0.1090f                                // support radius (rad)
#define WJ       39                                     // window half-width in bins

// ---- scratch (device globals; no allocation allowed) ----
__device__ float  g_gsum[NB * MM];
__device__ float  g_gp  [NB * NPAD];   // gsum[m]+gsum[M-m], zero-padded
__device__ float  g_gm  [NB * NPAD];   // gsum[m]-gsum[M-m]
__device__ float  g_Are [NJ * 1024];   // D_c(k)*Re F_b(k), shifted: index k-1
__device__ float  g_Aim [NJ * 1024];   // D_c(k)*Im F_b(k), shifted: index k-1
__device__ float  g_A0  [NJ];          // k = 0 term
__device__ float2 g_H   [NB * MM];     // H packed {c0, c1} per (b, m)
__device__ float  g_D   [2  * NK];
__device__ float  g_c   [MM];
__device__ float  g_s   [MM];
__device__ float  g_xg  [MM];

// XGRID exactly as numpy: v = i*(10/2049); xg = (2*pi*v)/10, f64 then cast f32
__device__ __forceinline__ float xgrid_f32(int m) {
    double v = (double)m * (10.0 / 2049.0);
    v = (6.283185307179586 * v) / 10.0;
    return (float)v;
}

// ============================================================================
// K_init: trig tables (f32), xgrid, Fourier multipliers D_c(kappa) (f32)
// ============================================================================
__global__ void k_init(const float* __restrict__ sh0, const float* __restrict__ am0,
                       const float* __restrict__ sh1, const float* __restrict__ am1) {
    int i = blockIdx.x * blockDim.x + threadIdx.x;
    if (i < MM) {
        double th = (6.283185307179586 * (double)i) / 2049.0;
        double s, c;
        sincos(th, &s, &c);
        g_c[i] = (float)c;
        g_s[i] = (float)s;
        g_xg[i] = xgrid_f32(i);
    }
    if (i < NK) {
        double tau = (double)((float)2.821e-5);
        double k2  = (double)i * (double)i;
        double dec2 = (M_PI / tau) * exp(2.0 * k2 * tau); // deconv^2
        double lo2p = 10.0 / (2.0 * M_PI);                // L/(2*pi)
        double s0 = 5.0 * (double)sh0[0];
        double s1 = 5.0 * (double)sh1[0];
        double m1 = -(double)am0[0] * 4.0 * M_PI / (k2 + s0 * s0);
        double den = k2 + s1 * s1;
        double m2 =  (double)am1[0] * 4.0 * M_PI / (den * den);
        g_D[i]      = (float)(lo2p * dec2 * m1);
        g_D[NK + i] = (float)(lo2p * dec2 * m2);
    }
}

// ============================================================================
// K_spread: gsum[b][m] = sum_n expf(-((x_n*c - xg_m)^2)/(4 tau))
// Tile of 128 bins per block; deterministic ordered candidate compaction.
// ============================================================================
__global__ __launch_bounds__(128) void k_spread(const float* __restrict__ x) {
    __shared__ float cand[NPT];
    __shared__ int   warp_cnt[4];

    int b    = blockIdx.x;
    int tile = blockIdx.y;          // 0..16
    int lo   = tile * 128;
    int t    = threadIdx.x;
    int lane = t & 31, w = t >> 5;

    const float* xb = x + b * NPT;
    float v[8];
    int flags = 0, cnt = 0;
    float fl = (float)(lo - 40), fh = (float)(lo + 127 + 40);
    #pragma unroll
    for (int i = 0; i < 8; ++i) {
        float xs = __fmul_rn(xb[t * 8 + i], C2PL_F);
        v[i] = xs;
        float cenf = xs * (float)(2049.0 / (2.0 * M_PI));
        int ok = (cenf >= fl) && (cenf <= fh);
        flags |= ok << i;
        cnt += ok;
    }
    int inc = cnt;
    #pragma unroll
    for (int o = 1; o < 32; o <<= 1) {
        int z = __shfl_up_sync(0xffffffffu, inc, o);
        if (lane >= o) inc += z;
    }
    if (lane == 31) warp_cnt[w] = inc;
    __syncthreads();
    int woff = 0;
    for (int i = 0; i < w; ++i) woff += warp_cnt[i];
    int ntot = warp_cnt[0] + warp_cnt[1] + warp_cnt[2] + warp_cnt[3];
    int off = woff + inc - cnt;
    #pragma unroll
    for (int i = 0; i < 8; ++i)
        if ((flags >> i) & 1) cand[off++] = v[i];
    __syncthreads();

    int m = lo + t;
    if (m < MM) {
        float xg = g_xg[m];
        float acc = 0.0f;
        for (int i = 0; i < ntot; ++i) {
            float d = __fsub_rn(cand[i], xg);
            if (fabsf(d) < WIN_R) {
                float arg = __fdiv_rn(__fmul_rn(d, d), FT32_F);
                acc += expf(-arg);
            }
        }
        g_gsum[b * MM + m] = acc;
    }
}

// ============================================================================
// K_prep: gp[mp]=g[mp]+g[M-mp], gm[mp]=g[mp]-g[M-mp]; mp=0 -> g[0]; pad zeros.
// ============================================================================
__global__ void k_prep() {
    int i = blockIdx.x * blockDim.x + threadIdx.x;
    if (i >= NB * NPAD) return;
    int b = i / NPAD, mp = i % NPAD;
    float gp = 0.0f, gm = 0.0f;
    if (mp == 0) {
        gp = g_gsum[b * MM];
    } else if (mp <= 1024) {
        float a = g_gsum[b * MM + mp];
        float c = g_gsum[b * MM + 2049 - mp];
        gp = a + c;
        gm = a - c;
    }
    g_gp[i] = gp;
    g_gm[i] = gm;
}

// ============================================================================
// K_fourier: warp per (k, 4-batch group) -> NK*4 = 4100 warps (occupancy!).
// Lane owns 4 consecutive mp -> LDG.128 operands; 32 FFMA per iteration.
// Epilogue folds D and writes shifted A layout.
// ============================================================================
__global__ __launch_bounds__(256) void k_fourier() {
    __shared__ float sc[MM], ss[MM];
    for (int i = threadIdx.x; i < MM; i += 256) { sc[i] = g_c[i]; ss[i] = g_s[i]; }
    __syncthreads();

    int w    = (blockIdx.x * 256 + threadIdx.x) >> 5;
    int lane = threadIdx.x & 31;
    if (w >= NK * 4) return;
    int k  = w >> 2;
    int b0 = (w & 3) * 4;

    int t   = (4 * lane * k) % MM;
    int stp = (128 * k) % MM;
    float fr[4], fi[4];
    #pragma unroll
    for (int i = 0; i < 4; ++i) { fr[i] = 0.0f; fi[i] = 0.0f; }

    int mp = lane * 4;
    #pragma unroll 1
    for (int it = 0; it < 9; ++it) {        // mp = 0..1151 (zero-padded)
        int u = t;
        float c0 = sc[u], s0 = ss[u]; u += k; if (u >= MM) u -= MM;
        float c1 = sc[u], s1 = ss[u]; u += k; if (u >= MM) u -= MM;
        float c2 = sc[u], s2 = ss[u]; u += k; if (u >= MM) u -= MM;
        float c3 = sc[u], s3 = ss[u];
        #pragma unroll
        for (int i = 0; i < 4; ++i) {
            float4 p = *(const float4*)&g_gp[(b0 + i) * NPAD + mp];
            float4 q = *(const float4*)&g_gm[(b0 + i) * NPAD + mp];
            fr[i] = fmaf(p.x, c0, fmaf(p.y, c1, fmaf(p.z, c2, fmaf(p.w, c3, fr[i]))));
            fi[i] = fmaf(q.x, s0, fmaf(q.y, s1, fmaf(q.z, s2, fmaf(q.w, s3, fi[i]))));
        }
        mp += 128;
        t += stp; if (t >= MM) t -= MM;
    }
    #pragma unroll
    for (int o = 16; o > 0; o >>= 1) {
        #pragma unroll
        for (int i = 0; i < 4; ++i) {
            fr[i] += __shfl_down_sync(0xffffffffu, fr[i], o);
            fi[i] += __shfl_down_sync(0xffffffffu, fi[i], o);
        }
    }
    if (lane == 0) {
        float D0 = g_D[k], D1 = g_D[NK + k];
        #pragma unroll
        for (int i = 0; i < 4; ++i) {
            int j0 = (b0 + i) * 2;
            float re =  fr[i];
            float im = -fi[i];
            if (k == 0) {
                g_A0[j0]     = D0 * re;
                g_A0[j0 + 1] = D1 * re;
            } else {
                g_Are[j0 * 1024 + k - 1]       = D0 * re;
                g_Aim[j0 * 1024 + k - 1]       = D0 * im;
                g_Are[(j0 + 1) * 1024 + k - 1] = D1 * re;
                g_Aim[(j0 + 1) * 1024 + k - 1] = D1 * im;
            }
        }
    }
}

// ============================================================================
// K_synth: warp per (m-pair, 4-j group = 2 batches x 2 channels) ->
// NK*8 = 8200 warps. Lane owns 4 consecutive k (LDG.128 on shifted A).
// H[m]=(A0+2(U-V))/M, H[M-m]=(A0+2(U+V))/M; packed float2 per (b,m).
// ============================================================================
__global__ __launch_bounds__(256) void k_synth() {
    __shared__ float sc[MM], ss[MM];
    for (int i = threadIdx.x; i < MM; i += 256) { sc[i] = g_c[i]; ss[i] = g_s[i]; }
    __syncthreads();

    int w    = (blockIdx.x * 256 + threadIdx.x) >> 5;
    int lane = threadIdx.x & 31;
    if (w >= NK * 8) return;
    int mp = w >> 3;                // 0..1024
    int gI = w & 7;                 // batch-pair group
    int b0 = gI * 2;                // batches b0, b0+1
    int j0 = gI * 4;                // j = j0..j0+3 (b0c0, b0c1, b1c0, b1c1)

    int t   = (mp * (1 + lane * 4)) % MM;   // theta index for k = 1 + 4*lane
    int stp = (128 * mp) % MM;
    float U[4], V[4];
    #pragma unroll
    for (int i = 0; i < 4; ++i) { U[i] = 0.0f; V[i] = 0.0f; }

    int kk = lane * 4;              // shifted index (k-1)
    #pragma unroll 1
    for (int it = 0; it < 8; ++it) {        // k = 1..1024
        int u = t;
        float c0 = sc[u], s0 = ss[u]; u += mp; if (u >= MM) u -= MM;
        float c1 = sc[u], s1 = ss[u]; u += mp; if (u >= MM) u -= MM;
        float c2 = sc[u], s2 = ss[u]; u += mp; if (u >= MM) u -= MM;
        float c3 = sc[u], s3 = ss[u];
        #pragma unroll
        for (int i = 0; i < 4; ++i) {
            float4 ar = *(const float4*)&g_Are[(j0 + i) * 1024 + kk];
            float4 ai = *(const float4*)&g_Aim[(j0 + i) * 1024 + kk];
            U[i] = fmaf(ar.x, c0, fmaf(ar.y, c1, fmaf(ar.z, c2, fmaf(ar.w, c3, U[i]))));
            V[i] = fmaf(ai.x, s0, fmaf(ai.y, s1, fmaf(ai.z, s2, fmaf(ai.w, s3, V[i]))));
        }
        kk += 128;
        t += stp; if (t >= MM) t -= MM;
    }
    #pragma unroll
    for (int o = 16; o > 0; o >>= 1) {
        #pragma unroll
        for (int i = 0; i < 4; ++i) {
            U[i] += __shfl_down_sync(0xffffffffu, U[i], o);
            V[i] += __shfl_down_sync(0xffffffffu, V[i], o);
        }
    }
    if (lane == 0) {
        const float inv = 1.0f / 2049.0f;
        #pragma unroll
        for (int bi = 0; bi < 2; ++bi) {
            int b  = b0 + bi;
            float a00 = g_A0[2 * b];
            float a01 = g_A0[2 * b + 1];
            float2 hm;
            hm.x = (a00 + 2.0f * (U[2 * bi]     - V[2 * bi]))     * inv;
            hm.y = (a01 + 2.0f * (U[2 * bi + 1] - V[2 * bi + 1])) * inv;
            g_H[b * MM + mp] = hm;
            if (mp) {
                float2 hp;
                hp.x = (a00 + 2.0f * (U[2 * bi]     + V[2 * bi]))     * inv;
                hp.y = (a01 + 2.0f * (U[2 * bi + 1] + V[2 * bi + 1])) * inv;
                g_H[b * MM + 2049 - mp] = hp;
            }
        }
    }
}

// ============================================================================
// K_out: fmm[b,n,c] = (1/M) * sum_{m in window} g[b,n,m] * H[b][m].c
// 2 threads per point (window halves), deterministic shfl combine; f64 acc.
// ============================================================================
__global__ __launch_bounds__(256) void k_out(const float* __restrict__ x,
                                             float* __restrict__ out) {
    int gid2 = blockIdx.x * blockDim.x + threadIdx.x;
    int gid  = gid2 >> 1;
    int half = gid2 & 1;
    if (gid >= NB * NPT) return;
    int b = gid / NPT;

    float xs = __fmul_rn(x[gid], C2PL_F);
    int cen = __float2int_rn(xs * (float)(2049.0 / (2.0 * M_PI)));

    const float2* Hb = g_H + b * MM;

    // half 0: j = -WJ..-1, half 1: j = 0..WJ
    int jlo = half ? 0 : -WJ;
    int jhi = half ? WJ : -1;

    double a0 = 0.0, a1 = 0.0;
    for (int j = jlo; j <= jhi; ++j) {
        int m = cen + j;
        if (m < 0 || m >= MM) continue;
        float d = __fsub_rn(xs, g_xg[m]);
        if (fabsf(d) < WIN_R) {
            float arg = __fdiv_rn(__fmul_rn(d, d), FT32_F);
            double gv = (double)expf(-arg);
            float2 h = Hb[m];
            a0 = fma(gv, (double)h.x, a0);
            a1 = fma(gv, (double)h.y, a1);
        }
    }
    // combine the two halves (lanes 2p, 2p+1)
    a0 += __shfl_down_sync(0xffffffffu, a0, 1);
    a1 += __shfl_down_sync(0xffffffffu, a1, 1);
    if (!half) {
        out[gid * 2 + 0] = (float)(a0 / 2049.0);
        out[gid * 2 + 1] = (float)(a1 / 2049.0);
    }
}

// ============================================================================
extern "C" void kernel_launch(void* const* d_in, const int* in_sizes, int n_in,
                              void* d_out, int out_size) {
    const float* x   = (const float*)d_in[0];
    const float* sh0 = (const float*)d_in[1];
    const float* am0 = (const float*)d_in[2];
    const float* sh1 = (const float*)d_in[3];
    const float* am1 = (const float*)d_in[4];
    float* out = (float*)d_out;

    k_init<<<(MM + 255) / 256, 256>>>(sh0, am0, sh1, am1);

    dim3 gs(NB, 17);
    k_spread<<<gs, 128>>>(x);

    k_prep<<<(NB * NPAD + 255) / 256, 256>>>();

    // forward transform + D fold: NK*4 warps, 8 warps/block
    k_fourier<<<(NK * 4 + 7) / 8, 256>>>();

    // inverse synthesis: NK*8 warps, 8 warps/block
    k_synth<<<NK, 256>>>();

    // interpolate back to points: 2 threads per point
    k_out<<<(NB * NPT * 2 + 255) / 256, 256>>>(x, out);
}

// round 11
// speedup vs baseline: 1.1666x; 1.1666x over previous
#include <cuda_runtime.h>
#include <math.h>

#define MM    2049        // mesh points
#define NK    1025        // kappa = 0..1024 (Hermitian half)
#define NB    16          // batch
#define NPT   1024        // points per batch
#define NJ    32          // (b,c) pairs: j = b*2 + c
#define NP4   512         // k-pairs (k=1..1024 -> 512 pairs)

// ---- f32-faithful constants ----
#define C2PL_F   ((float)(2.0 * M_PI / 10.0))          // 2*pi/L as f32
#define FT32_F   ((float)(4.0 * 2.821e-5))             // 4*tau as f32
#define WIN_R    0.1090f                                // support radius (rad)
#define WJ       39                                     // window half-width in bins

// ---- scratch (device globals; no allocation allowed) ----
__device__ float  g_gsum[NB * MM];
__device__ float2 g_t2 [NK * NB];      // [mp][b] = {gp, gm}
__device__ float2 g_A4 [NP4 * NJ * 2]; // [(p*32+j)*2 + comp] = {Are, Aim}, k = 2p+1+comp
__device__ float  g_A0 [NJ];           // k = 0 term (D*F0)
__device__ float2 g_H  [NB * MM];      // H packed {c0, c1} per (b, m)
__device__ float  g_D  [2  * NK];
__device__ float2 g_cs [MM];           // {cos, sin}(2*pi*i/M)
__device__ float  g_xg [MM];

// XGRID exactly as numpy: v = i*(10/2049); xg = (2*pi*v)/10, f64 then cast f32
__device__ __forceinline__ float xgrid_f32(int m) {
    double v = (double)m * (10.0 / 2049.0);
    v = (6.283185307179586 * v) / 10.0;
    return (float)v;
}

// ============================================================================
// K_init: trig table (f32 float2), xgrid, Fourier multipliers D_c(kappa)
// ============================================================================
__global__ void k_init(const float* __restrict__ sh0, const float* __restrict__ am0,
                       const float* __restrict__ sh1, const float* __restrict__ am1) {
    int i = blockIdx.x * blockDim.x + threadIdx.x;
    if (i < MM) {
        double th = (6.283185307179586 * (double)i) / 2049.0;
        double s, c;
        sincos(th, &s, &c);
        g_cs[i] = make_float2((float)c, (float)s);
        g_xg[i] = xgrid_f32(i);
    }
    if (i < NK) {
        double tau = (double)((float)2.821e-5);
        double k2  = (double)i * (double)i;
        double dec2 = (M_PI / tau) * exp(2.0 * k2 * tau); // deconv^2
        double lo2p = 10.0 / (2.0 * M_PI);                // L/(2*pi)
        double s0 = 5.0 * (double)sh0[0];
        double s1 = 5.0 * (double)sh1[0];
        double m1 = -(double)am0[0] * 4.0 * M_PI / (k2 + s0 * s0);
        double den = k2 + s1 * s1;
        double m2 =  (double)am1[0] * 4.0 * M_PI / (den * den);
        g_D[i]      = (float)(lo2p * dec2 * m1);
        g_D[NK + i] = (float)(lo2p * dec2 * m2);
    }
}

// ============================================================================
// K_spread: gsum[b][m] = sum_n expf(-((x_n*c - xg_m)^2)/(4 tau))
// Tile of 128 bins per block; deterministic ordered candidate compaction.
// ============================================================================
__global__ __launch_bounds__(128) void k_spread(const float* __restrict__ x) {
    __shared__ float cand[NPT];
    __shared__ int   warp_cnt[4];

    int b    = blockIdx.x;
    int tile = blockIdx.y;          // 0..16
    int lo   = tile * 128;
    int t    = threadIdx.x;
    int lane = t & 31, w = t >> 5;

    const float* xb = x + b * NPT;
    float v[8];
    int flags = 0, cnt = 0;
    float fl = (float)(lo - 40), fh = (float)(lo + 127 + 40);
    #pragma unroll
    for (int i = 0; i < 8; ++i) {
        float xs = __fmul_rn(xb[t * 8 + i], C2PL_F);
        v[i] = xs;
        float cenf = xs * (float)(2049.0 / (2.0 * M_PI));
        int ok = (cenf >= fl) && (cenf <= fh);
        flags |= ok << i;
        cnt += ok;
    }
    int inc = cnt;
    #pragma unroll
    for (int o = 1; o < 32; o <<= 1) {
        int z = __shfl_up_sync(0xffffffffu, inc, o);
        if (lane >= o) inc += z;
    }
    if (lane == 31) warp_cnt[w] = inc;
    __syncthreads();
    int woff = 0;
    for (int i = 0; i < w; ++i) woff += warp_cnt[i];
    int ntot = warp_cnt[0] + warp_cnt[1] + warp_cnt[2] + warp_cnt[3];
    int off = woff + inc - cnt;
    #pragma unroll
    for (int i = 0; i < 8; ++i)
        if ((flags >> i) & 1) cand[off++] = v[i];
    __syncthreads();

    int m = lo + t;
    if (m < MM) {
        float xg = g_xg[m];
        float acc = 0.0f;
        for (int i = 0; i < ntot; ++i) {
            float d = __fsub_rn(cand[i], xg);
            if (fabsf(d) < WIN_R) {
                float arg = __fdiv_rn(__fmul_rn(d, d), FT32_F);
                acc += expf(-arg);
            }
        }
        g_gsum[b * MM + m] = acc;
    }
}

// ============================================================================
// K_prep: g_t2[mp][b] = {g[mp]+g[M-mp], g[mp]-g[M-mp]};  mp=0 -> {g[0], 0}
// ============================================================================
__global__ void k_prep() {
    int i = blockIdx.x * blockDim.x + threadIdx.x;
    if (i >= NK * NB) return;
    int mp = i >> 4, b = i & 15;
    float2 v;
    if (mp == 0) {
        v = make_float2(g_gsum[b * MM], 0.0f);
    } else {
        float a = g_gsum[b * MM + mp];
        float c = g_gsum[b * MM + 2049 - mp];
        v = make_float2(a + c, a - c);
    }
    g_t2[mp * NB + b] = v;
}

// ============================================================================
// K_fourier: warp per (k, mp-half). Lanes = 16 batches x 2 mp-parities.
// Trig access is warp-uniform (broadcast LDS, conflict-free); g operand is
// one coalesced LDG.64 per iter. Each lane sequentially owns its batch sum.
// Epilogue folds D and writes the k-paired A layout (+ g_A0 for k=0).
// ============================================================================
__global__ __launch_bounds__(256) void k_fourier() {
    __shared__ float2 scs[MM];
    __shared__ float  sbC[4][32], sbS[4][32];

    for (int i = threadIdx.x; i < MM; i += 256) scs[i] = g_cs[i];
    __syncthreads();

    int wib  = threadIdx.x >> 5;        // 0..7
    int lane = threadIdx.x & 31;
    int pair = wib >> 1;                // 0..3 (k slot in block)
    int half = wib & 1;
    int k    = blockIdx.x * 4 + pair;
    bool valid = (k < NK);

    float accC = 0.0f, accS = 0.0f;
    if (valid) {
        int b   = lane & 15;
        int par = lane >> 4;
        int start = half * 513;
        int cnt   = half ? 512 : 513;
        int iters = (cnt - par + 1) >> 1;
        int mp0   = start + par;

        int t   = (k * mp0) % MM;
        int stp = (2 * k) % MM;
        const float2* gt = g_t2 + mp0 * NB + b;

        #pragma unroll 4
        for (int it = 0; it < iters; ++it) {
            float2 cs = scs[t];
            float2 g  = *gt;
            accC = fmaf(g.x, cs.x, accC);
            accS = fmaf(g.y, cs.y, accS);
            gt += 2 * NB;
            t += stp; if (t >= MM) t -= MM;
        }
        // combine mp parities (lanes b and b+16 both end with the total)
        accC += __shfl_xor_sync(0xffffffffu, accC, 16);
        accS += __shfl_xor_sync(0xffffffffu, accS, 16);
    }
    if (valid && half) { sbC[pair][lane] = accC; sbS[pair][lane] = accS; }
    __syncthreads();
    if (valid && !half) {
        accC += sbC[pair][lane];
        accS += sbS[pair][lane];
        // lane j -> (b = j>>1, c = j&1)
        int j = lane;
        int b = j >> 1, c = j & 1;
        float re =  __shfl_sync(0xffffffffu, accC, b);
        float im = -__shfl_sync(0xffffffffu, accS, b);
        float D  = g_D[c * NK + k];
        if (k == 0) {
            g_A0[j] = D * re;
        } else {
            int p    = (k - 1) >> 1;
            int comp = (k - 1) & 1;
            g_A4[(p * NJ + j) * 2 + comp] = make_float2(D * re, D * im);
        }
    }
}

// ============================================================================
// K_synth: warp per (mp, k-half). Lanes = 32 j's. Per iter: one LDG.128
// (A pair for 2 k's), two broadcast LDS.64, 4 FFMA.
// H[mp]=(A0+2(U-V))/M, H[M-mp]=(A0+2(U+V))/M; packed float2 per (b,m).
// ============================================================================
__global__ __launch_bounds__(256) void k_synth() {
    __shared__ float2 scs[MM];
    __shared__ float  sbU[4][32], sbV[4][32];

    for (int i = threadIdx.x; i < MM; i += 256) scs[i] = g_cs[i];
    __syncthreads();

    int wib  = threadIdx.x >> 5;
    int lane = threadIdx.x & 31;        // = j
    int pair = wib >> 1;
    int half = wib & 1;
    int mp   = blockIdx.x * 4 + pair;
    bool valid = (mp < NK);

    float U = 0.0f, V = 0.0f;
    if (valid) {
        int p0 = half * 256;            // k-pairs 0..255 / 256..511
        int k0 = 2 * p0 + 1;
        int t0 = (mp * k0) % MM;
        int t1 = t0 + mp; if (t1 >= MM) t1 -= MM;
        int stp = (2 * mp) % MM;
        const float4* ap = (const float4*)g_A4 + p0 * NJ + lane;

        #pragma unroll 4
        for (int it = 0; it < 256; ++it) {
            float4 a = *ap;
            float2 cs0 = scs[t0];
            float2 cs1 = scs[t1];
            U = fmaf(a.x, cs0.x, U);
            V = fmaf(a.y, cs0.y, V);
            U = fmaf(a.z, cs1.x, U);
            V = fmaf(a.w, cs1.y, V);
            ap += NJ;
            t0 += stp; if (t0 >= MM) t0 -= MM;
            t1 += stp; if (t1 >= MM) t1 -= MM;
        }
    }
    if (valid && half) { sbU[pair][lane] = U; sbV[pair][lane] = V; }
    __syncthreads();
    if (valid && !half) {
        U += sbU[pair][lane];
        V += sbV[pair][lane];
        const float inv = 1.0f / 2049.0f;
        float a0 = g_A0[lane];
        float hm = (a0 + 2.0f * (U - V)) * inv;
        float hp = (a0 + 2.0f * (U + V)) * inv;
        float hmy = __shfl_down_sync(0xffffffffu, hm, 1);
        float hpy = __shfl_down_sync(0xffffffffu, hp, 1);
        if ((lane & 1) == 0) {
            int b = lane >> 1;
            g_H[b * MM + mp] = make_float2(hm, hmy);
            if (mp)
                g_H[b * MM + 2049 - mp] = make_float2(hp, hpy);
        }
    }
}

// ============================================================================
// K_out: fmm[b,n,c] = (1/M) * sum_{m in window} g[b,n,m] * H[b][m].c
// float2 H loads; f64 accumulator (cheap).
// ============================================================================
__global__ __launch_bounds__(256) void k_out(const float* __restrict__ x,
                                             float* __restrict__ out) {
    int gid = blockIdx.x * blockDim.x + threadIdx.x;
    if (gid >= NB * NPT) return;
    int b = gid / NPT;

    float xs = __fmul_rn(x[gid], C2PL_F);
    int cen = __float2int_rn(xs * (float)(2049.0 / (2.0 * M_PI)));

    const float2* Hb = g_H + b * MM;

    double a0 = 0.0, a1 = 0.0;
    #pragma unroll 4
    for (int j = -WJ; j <= WJ; ++j) {
        int m = cen + j;
        if (m < 0 || m >= MM) continue;
        float d = __fsub_rn(xs, g_xg[m]);
        if (fabsf(d) < WIN_R) {
            float arg = __fdiv_rn(__fmul_rn(d, d), FT32_F);
            double gv = (double)expf(-arg);
            float2 h = Hb[m];
            a0 = fma(gv, (double)h.x, a0);
            a1 = fma(gv, (double)h.y, a1);
        }
    }
    out[gid * 2 + 0] = (float)(a0 / 2049.0);
    out[gid * 2 + 1] = (float)(a1 / 2049.0);
}

// ============================================================================
extern "C" void kernel_launch(void* const* d_in, const int* in_sizes, int n_in,
                              void* d_out, int out_size) {
    const float* x   = (const float*)d_in[0];
    const float* sh0 = (const float*)d_in[1];
    const float* am0 = (const float*)d_in[2];
    const float* sh1 = (const float*)d_in[3];
    const float* am1 = (const float*)d_in[4];
    float* out = (float*)d_out;

    k_init<<<(MM + 255) / 256, 256>>>(sh0, am0, sh1, am1);

    dim3 gs(NB, 17);
    k_spread<<<gs, 128>>>(x);

    k_prep<<<(NK * NB + 255) / 256, 256>>>();

    // forward transform + D fold: 4 k per block, 2 half-warps each
    k_fourier<<<(NK + 3) / 4, 256>>>();

    // inverse synthesis: 4 mp per block, 2 half-warps each
    k_synth<<<(NK + 3) / 4, 256>>>();

    k_out<<<(NB * NPT + 255) / 256, 256>>>(x, out);
}

// round 12
// speedup vs baseline: 1.4734x; 1.2629x over previous
#include <cuda_runtime.h>
#include <math.h>

#define MM    2049        // mesh points
#define NK    1025        // kappa = 0..1024 (Hermitian half)
#define NB    16          // batch
#define NPT   1024        // points per batch
#define NJ    32          // (b,c) pairs: j = b*2 + c
#define NP4   512         // k-pairs (k=1..1024 -> 512 pairs)
#define NCH   5           // fourier mp-chunks (5 x 205 = 1025)
#define CHL   205         // chunk length
#define NE    8           // synth k-eighths (8 x 64 pairs = 512)

// ---- f32-faithful constants ----
#define C2PL_F   ((float)(2.0 * M_PI / 10.0))          // 2*pi/L as f32
#define FT32_F   ((float)(4.0 * 2.821e-5))             // 4*tau as f32
#define WIN_R    0.1090f                                // support radius (rad)
#define WJ       39                                     // window half-width in bins

// ---- scratch (device globals; no allocation allowed) ----
__device__ float  g_gsum[NB * MM];
__device__ float2 g_t2 [NK * NB];        // [mp][b] = {gp, gm}
__device__ float2 g_pF [NCH * NK * NB];  // fourier partials {C, S}
__device__ float2 g_A4 [NP4 * NJ * 2];   // [(p*32+j)*2+comp] = {Are, Aim}, k=2p+1+comp
__device__ float  g_A0 [NJ];             // k = 0 term (D*F0)
__device__ float2 g_pUV[NE * NK * NJ];   // synth partials {U, V}
__device__ float2 g_H  [NB * MM];        // H packed {c0, c1} per (b, m)
__device__ float  g_D  [2  * NK];
__device__ float2 g_cs [MM];             // {cos, sin}(2*pi*i/M)
__device__ float  g_xg [MM];

// XGRID exactly as numpy: v = i*(10/2049); xg = (2*pi*v)/10, f64 then cast f32
__device__ __forceinline__ float xgrid_f32(int m) {
    double v = (double)m * (10.0 / 2049.0);
    v = (6.283185307179586 * v) / 10.0;
    return (float)v;
}

// ============================================================================
// K_init: trig table, xgrid, Fourier multipliers D_c(kappa)
// ============================================================================
__global__ void k_init(const float* __restrict__ sh0, const float* __restrict__ am0,
                       const float* __restrict__ sh1, const float* __restrict__ am1) {
    int i = blockIdx.x * blockDim.x + threadIdx.x;
    if (i < MM) {
        double th = (6.283185307179586 * (double)i) / 2049.0;
        double s, c;
        sincos(th, &s, &c);
        g_cs[i] = make_float2((float)c, (float)s);
        g_xg[i] = xgrid_f32(i);
    }
    if (i < NK) {
        double tau = (double)((float)2.821e-5);
        double k2  = (double)i * (double)i;
        double dec2 = (M_PI / tau) * exp(2.0 * k2 * tau); // deconv^2
        double lo2p = 10.0 / (2.0 * M_PI);                // L/(2*pi)
        double s0 = 5.0 * (double)sh0[0];
        double s1 = 5.0 * (double)sh1[0];
        double m1 = -(double)am0[0] * 4.0 * M_PI / (k2 + s0 * s0);
        double den = k2 + s1 * s1;
        double m2 =  (double)am1[0] * 4.0 * M_PI / (den * den);
        g_D[i]      = (float)(lo2p * dec2 * m1);
        g_D[NK + i] = (float)(lo2p * dec2 * m2);
    }
}

// ============================================================================
// K_spread: gsum[b][m] = sum_n expf(-((x_n*c - xg_m)^2)/(4 tau))
// ============================================================================
__global__ __launch_bounds__(128) void k_spread(const float* __restrict__ x) {
    __shared__ float cand[NPT];
    __shared__ int   warp_cnt[4];

    int b    = blockIdx.x;
    int tile = blockIdx.y;          // 0..16
    int lo   = tile * 128;
    int t    = threadIdx.x;
    int lane = t & 31, w = t >> 5;

    const float* xb = x + b * NPT;
    float v[8];
    int flags = 0, cnt = 0;
    float fl = (float)(lo - 40), fh = (float)(lo + 127 + 40);
    #pragma unroll
    for (int i = 0; i < 8; ++i) {
        float xs = __fmul_rn(xb[t * 8 + i], C2PL_F);
        v[i] = xs;
        float cenf = xs * (float)(2049.0 / (2.0 * M_PI));
        int ok = (cenf >= fl) && (cenf <= fh);
        flags |= ok << i;
        cnt += ok;
    }
    int inc = cnt;
    #pragma unroll
    for (int o = 1; o < 32; o <<= 1) {
        int z = __shfl_up_sync(0xffffffffu, inc, o);
        if (lane >= o) inc += z;
    }
    if (lane == 31) warp_cnt[w] = inc;
    __syncthreads();
    int woff = 0;
    for (int i = 0; i < w; ++i) woff += warp_cnt[i];
    int ntot = warp_cnt[0] + warp_cnt[1] + warp_cnt[2] + warp_cnt[3];
    int off = woff + inc - cnt;
    #pragma unroll
    for (int i = 0; i < 8; ++i)
        if ((flags >> i) & 1) cand[off++] = v[i];
    __syncthreads();

    int m = lo + t;
    if (m < MM) {
        float xg = g_xg[m];
        float acc = 0.0f;
        for (int i = 0; i < ntot; ++i) {
            float d = __fsub_rn(cand[i], xg);
            if (fabsf(d) < WIN_R) {
                float arg = __fdiv_rn(__fmul_rn(d, d), FT32_F);
                acc += expf(-arg);
            }
        }
        g_gsum[b * MM + m] = acc;
    }
}

// ============================================================================
// K_prep: g_t2[mp][b] = {g[mp]+g[M-mp], g[mp]-g[M-mp]};  mp=0 -> {g[0], 0}
// ============================================================================
__global__ void k_prep() {
    int i = blockIdx.x * blockDim.x + threadIdx.x;
    if (i >= NK * NB) return;
    int mp = i >> 4, b = i & 15;
    float2 v;
    if (mp == 0) {
        v = make_float2(g_gsum[b * MM], 0.0f);
    } else {
        float a = g_gsum[b * MM + mp];
        float c = g_gsum[b * MM + 2049 - mp];
        v = make_float2(a + c, a - c);
    }
    g_t2[mp * NB + b] = v;
}

// ============================================================================
// K_fourier: grid (129 k-octets, 5 mp-chunks). Warp = one k; lanes = 16 b x
// 2 mp-parities. g_t2 chunk (27KB) is block-shared via L1 (__ldg); trig from
// smem broadcast table. Writes partials g_pF[chunk][k][b].
// ============================================================================
__global__ __launch_bounds__(256) void k_fourier() {
    __shared__ float2 scs[MM];
    for (int i = threadIdx.x; i < MM; i += 256) scs[i] = g_cs[i];
    __syncthreads();

    int w    = threadIdx.x >> 5;
    int lane = threadIdx.x & 31;
    int k    = blockIdx.x * 8 + w;
    int y    = blockIdx.y;          // chunk
    if (k >= NK) return;

    int start = y * CHL;            // 5 x 205 = 1025 exact
    int b   = lane & 15;
    int par = lane >> 4;

    int t    = (k * (start + par)) % MM;
    int stp  = (2 * k) % MM;
    const float2* gt = g_t2 + (start + par) * NB + b;

    float C = 0.0f, S = 0.0f;
    int iters = (CHL - par + 1) >> 1;   // 103 / 102
    #pragma unroll 4
    for (int it = 0; it < iters; ++it) {
        float2 cs = scs[t];
        float2 g  = __ldg(gt);
        C = fmaf(g.x, cs.x, C);
        S = fmaf(g.y, cs.y, S);
        gt += 2 * NB;
        t += stp; if (t >= MM) t -= MM;
    }
    C += __shfl_xor_sync(0xffffffffu, C, 16);
    S += __shfl_xor_sync(0xffffffffu, S, 16);
    if (lane < 16)
        g_pF[(y * NK + k) * NB + b] = make_float2(C, S);
}

// ============================================================================
// K_comb: combine fourier chunk partials, fold D, write A (k-paired) + A0.
// Thread per (k, b).
// ============================================================================
__global__ void k_comb() {
    int i = blockIdx.x * blockDim.x + threadIdx.x;
    if (i >= NK * NB) return;
    int k = i >> 4, b = i & 15;
    float C = 0.0f, S = 0.0f;
    #pragma unroll
    for (int y = 0; y < NCH; ++y) {
        float2 p = g_pF[(y * NK + k) * NB + b];
        C += p.x; S += p.y;
    }
    float re =  C;
    float im = -S;
    float D0 = g_D[k], D1 = g_D[NK + k];
    int j0 = 2 * b, j1 = 2 * b + 1;
    if (k == 0) {
        g_A0[j0] = D0 * re;
        g_A0[j1] = D1 * re;
    } else {
        int p    = (k - 1) >> 1;
        int comp = (k - 1) & 1;
        g_A4[(p * NJ + j0) * 2 + comp] = make_float2(D0 * re, D0 * im);
        g_A4[(p * NJ + j1) * 2 + comp] = make_float2(D1 * re, D1 * im);
    }
}

// ============================================================================
// K_synth: grid (65 mp-16-tiles, 8 k-eighths of 64 pairs). Warp = 2 mp
// sharing each A float4 (L1-resident 32KB eighth via __ldg); lane = j.
// Trig from smem broadcast table. Writes partials g_pUV[e][mp][j].
// ============================================================================
__global__ __launch_bounds__(256) void k_synth() {
    __shared__ float2 scs[MM];
    for (int i = threadIdx.x; i < MM; i += 256) scs[i] = g_cs[i];
    __syncthreads();

    int w    = threadIdx.x >> 5;
    int lane = threadIdx.x & 31;        // = j
    int e    = blockIdx.y;
    int mpA  = blockIdx.x * 16 + 2 * w;
    int mpB  = mpA + 1;
    bool vA = (mpA < NK), vB = (mpB < NK);
    if (!vA) return;                    // mpB >= NK only possible when mpA == 1024

    int p0 = e * 64;                    // pairs p0..p0+63, k = 2p+1, 2p+2
    int k0 = 2 * p0 + 1;

    int tA  = (int)(((long long)mpA * k0) % MM);
    int tA2 = tA + mpA; if (tA2 >= MM) tA2 -= MM;
    int sA  = (2 * mpA) % MM;
    int tB  = (int)(((long long)mpB * k0) % MM);
    int tB2 = tB + mpB; if (tB2 >= MM) tB2 -= MM;
    int sB  = (2 * mpB) % MM;

    const float4* ap = (const float4*)g_A4 + p0 * NJ + lane;

    float UA = 0.f, VA = 0.f, UB = 0.f, VB = 0.f;
    #pragma unroll 4
    for (int it = 0; it < 64; ++it) {
        float4 a = __ldg(ap);
        float2 cA0 = scs[tA], cA1 = scs[tA2];
        UA = fmaf(a.x, cA0.x, UA);
        VA = fmaf(a.y, cA0.y, VA);
        UA = fmaf(a.z, cA1.x, UA);
        VA = fmaf(a.w, cA1.y, VA);
        if (vB) {
            float2 cB0 = scs[tB], cB1 = scs[tB2];
            UB = fmaf(a.x, cB0.x, UB);
            VB = fmaf(a.y, cB0.y, VB);
            UB = fmaf(a.z, cB1.x, UB);
            VB = fmaf(a.w, cB1.y, VB);
        }
        ap += NJ;
        tA += sA;  if (tA  >= MM) tA  -= MM;
        tA2 += sA; if (tA2 >= MM) tA2 -= MM;
        tB += sB;  if (tB  >= MM) tB  -= MM;
        tB2 += sB; if (tB2 >= MM) tB2 -= MM;
    }
    g_pUV[(e * NK + mpA) * NJ + lane] = make_float2(UA, VA);
    if (vB)
        g_pUV[(e * NK + mpB) * NJ + lane] = make_float2(UB, VB);
}

// ============================================================================
// K_hcomb: combine synth partials, build packed H.
// Thread per (mp, b): j0 = 2b (ch0), j1 = 2b+1 (ch1).
// H[mp]=(A0+2(U-V))/M, H[M-mp]=(A0+2(U+V))/M.
// ============================================================================
__global__ void k_hcomb() {
    int i = blockIdx.x * blockDim.x + threadIdx.x;
    if (i >= NK * NB) return;
    int mp = i >> 4, b = i & 15;
    int j0 = 2 * b, j1 = 2 * b + 1;
    float U0 = 0.f, V0 = 0.f, U1 = 0.f, V1 = 0.f;
    #pragma unroll
    for (int e = 0; e < NE; ++e) {
        float2 p0 = g_pUV[(e * NK + mp) * NJ + j0];
        float2 p1 = g_pUV[(e * NK + mp) * NJ + j1];
        U0 += p0.x; V0 += p0.y;
        U1 += p1.x; V1 += p1.y;
    }
    const float inv = 1.0f / 2049.0f;
    float a00 = g_A0[j0], a01 = g_A0[j1];
    float2 hm = make_float2((a00 + 2.0f * (U0 - V0)) * inv,
                            (a01 + 2.0f * (U1 - V1)) * inv);
    g_H[b * MM + mp] = hm;
    if (mp) {
        float2 hp = make_float2((a00 + 2.0f * (U0 + V0)) * inv,
                                (a01 + 2.0f * (U1 + V1)) * inv);
        g_H[b * MM + 2049 - mp] = hp;
    }
}

// ============================================================================
// K_out: fmm[b,n,c] = (1/M) * sum_{m in window} g[b,n,m] * H[b][m].c
// ============================================================================
__global__ __launch_bounds__(256) void k_out(const float* __restrict__ x,
                                             float* __restrict__ out) {
    int gid = blockIdx.x * blockDim.x + threadIdx.x;
    if (gid >= NB * NPT) return;
    int b = gid / NPT;

    float xs = __fmul_rn(x[gid], C2PL_F);
    int cen = __float2int_rn(xs * (float)(2049.0 / (2.0 * M_PI)));

    const float2* Hb = g_H + b * MM;

    double a0 = 0.0, a1 = 0.0;
    #pragma unroll 4
    for (int j = -WJ; j <= WJ; ++j) {
        int m = cen + j;
        if (m < 0 || m >= MM) continue;
        float d = __fsub_rn(xs, g_xg[m]);
        if (fabsf(d) < WIN_R) {
            float arg = __fdiv_rn(__fmul_rn(d, d), FT32_F);
            double gv = (double)expf(-arg);
            float2 h = Hb[m];
            a0 = fma(gv, (double)h.x, a0);
            a1 = fma(gv, (double)h.y, a1);
        }
    }
    out[gid * 2 + 0] = (float)(a0 / 2049.0);
    out[gid * 2 + 1] = (float)(a1 / 2049.0);
}

// ============================================================================
extern "C" void kernel_launch(void* const* d_in, const int* in_sizes, int n_in,
                              void* d_out, int out_size) {
    const float* x   = (const float*)d_in[0];
    const float* sh0 = (const float*)d_in[1];
    const float* am0 = (const float*)d_in[2];
    const float* sh1 = (const float*)d_in[3];
    const float* am1 = (const float*)d_in[4];
    float* out = (float*)d_out;

    k_init<<<(MM + 255) / 256, 256>>>(sh0, am0, sh1, am1);

    dim3 gsp(NB, 17);
    k_spread<<<gsp, 128>>>(x);

    k_prep<<<(NK * NB + 255) / 256, 256>>>();

    dim3 gf(129, NCH);                  // 8 k per block x 5 mp-chunks
    k_fourier<<<gf, 256>>>();
    k_comb<<<(NK * NB + 255) / 256, 256>>>();

    dim3 gsy(65, NE);                   // 16 mp per block x 8 k-eighths
    k_synth<<<gsy, 256>>>();
    k_hcomb<<<(NK * NB + 255) / 256, 256>>>();

    k_out<<<(NB * NPT + 255) / 256, 256>>>(x, out);
}

// round 13
// speedup vs baseline: 1.4844x; 1.0075x over previous
#include <cuda_runtime.h>
#include <math.h>

#define MM    2049        // mesh points
#define NK    1025        // kappa = 0..1024 (Hermitian half)
#define NKP   1040        // padded mp count for fourier tiling
#define NB    16          // batch
#define NPT   1024        // points per batch
#define NJ    32          // (b,c) pairs: j = b*2 + c
#define NP4   512         // k-pairs (k=1..1024 -> 512 pairs)
#define NCH   10          // fourier mp-chunks
#define CHL   104         // chunk length (10 x 104 = 1040)
#define NE    16          // synth k-slices (16 x 32 pairs = 512)

// ---- f32-faithful constants ----
#define C2PL_F   ((float)(2.0 * M_PI / 10.0))          // 2*pi/L as f32
#define FT32_F   ((float)(4.0 * 2.821e-5))             // 4*tau as f32
#define WIN_R    0.1090f                                // support radius (rad)
#define WJ       39                                     // window half-width in bins

// ---- scratch (device globals; no allocation allowed) ----
__device__ float  g_gsum[NB * MM];
__device__ float2 g_t2 [NKP * NB];       // [mp][b] = {gp, gm}, zero-padded
__device__ float2 g_pF [NCH * NK * NB];  // fourier partials {C, S}
__device__ float2 g_A4 [NP4 * NJ * 2];   // [(p*32+j)*2+comp] = {Are, Aim}, k=2p+1+comp
__device__ float  g_A0 [NJ];             // k = 0 term (D*F0)
__device__ float2 g_pUV[NE * NK * NJ];   // synth partials {U, V}
__device__ float2 g_H  [NB * MM];        // H packed {c0, c1} per (b, m)
__device__ float  g_D  [2  * NK];
__device__ float2 g_cs [MM];             // {cos, sin}(2*pi*i/M)
__device__ float  g_xg [MM];

// XGRID exactly as numpy: v = i*(10/2049); xg = (2*pi*v)/10, f64 then cast f32
__device__ __forceinline__ float xgrid_f32(int m) {
    double v = (double)m * (10.0 / 2049.0);
    v = (6.283185307179586 * v) / 10.0;
    return (float)v;
}

// ============================================================================
// K_init: trig table, xgrid, Fourier multipliers D_c(kappa)
// ============================================================================
__global__ void k_init(const float* __restrict__ sh0, const float* __restrict__ am0,
                       const float* __restrict__ sh1, const float* __restrict__ am1) {
    int i = blockIdx.x * blockDim.x + threadIdx.x;
    if (i < MM) {
        double th = (6.283185307179586 * (double)i) / 2049.0;
        double s, c;
        sincos(th, &s, &c);
        g_cs[i] = make_float2((float)c, (float)s);
        g_xg[i] = xgrid_f32(i);
    }
    if (i < NK) {
        double tau = (double)((float)2.821e-5);
        double k2  = (double)i * (double)i;
        double dec2 = (M_PI / tau) * exp(2.0 * k2 * tau); // deconv^2
        double lo2p = 10.0 / (2.0 * M_PI);                // L/(2*pi)
        double s0 = 5.0 * (double)sh0[0];
        double s1 = 5.0 * (double)sh1[0];
        double m1 = -(double)am0[0] * 4.0 * M_PI / (k2 + s0 * s0);
        double den = k2 + s1 * s1;
        double m2 =  (double)am1[0] * 4.0 * M_PI / (den * den);
        g_D[i]      = (float)(lo2p * dec2 * m1);
        g_D[NK + i] = (float)(lo2p * dec2 * m2);
    }
}

// ============================================================================
// K_spread: gsum[b][m] = sum_n expf(-((x_n*c - xg_m)^2)/(4 tau))
// ============================================================================
__global__ __launch_bounds__(128) void k_spread(const float* __restrict__ x) {
    __shared__ float cand[NPT];
    __shared__ int   warp_cnt[4];

    int b    = blockIdx.x;
    int tile = blockIdx.y;          // 0..16
    int lo   = tile * 128;
    int t    = threadIdx.x;
    int lane = t & 31, w = t >> 5;

    const float* xb = x + b * NPT;
    float v[8];
    int flags = 0, cnt = 0;
    float fl = (float)(lo - 40), fh = (float)(lo + 127 + 40);
    #pragma unroll
    for (int i = 0; i < 8; ++i) {
        float xs = __fmul_rn(xb[t * 8 + i], C2PL_F);
        v[i] = xs;
        float cenf = xs * (float)(2049.0 / (2.0 * M_PI));
        int ok = (cenf >= fl) && (cenf <= fh);
        flags |= ok << i;
        cnt += ok;
    }
    int inc = cnt;
    #pragma unroll
    for (int o = 1; o < 32; o <<= 1) {
        int z = __shfl_up_sync(0xffffffffu, inc, o);
        if (lane >= o) inc += z;
    }
    if (lane == 31) warp_cnt[w] = inc;
    __syncthreads();
    int woff = 0;
    for (int i = 0; i < w; ++i) woff += warp_cnt[i];
    int ntot = warp_cnt[0] + warp_cnt[1] + warp_cnt[2] + warp_cnt[3];
    int off = woff + inc - cnt;
    #pragma unroll
    for (int i = 0; i < 8; ++i)
        if ((flags >> i) & 1) cand[off++] = v[i];
    __syncthreads();

    int m = lo + t;
    if (m < MM) {
        float xg = g_xg[m];
        float acc = 0.0f;
        for (int i = 0; i < ntot; ++i) {
            float d = __fsub_rn(cand[i], xg);
            if (fabsf(d) < WIN_R) {
                float arg = __fdiv_rn(__fmul_rn(d, d), FT32_F);
                acc += expf(-arg);
            }
        }
        g_gsum[b * MM + m] = acc;
    }
}

// ============================================================================
// K_prep: g_t2[mp][b] = {g[mp]+g[M-mp], g[mp]-g[M-mp]}; mp=0 -> {g[0],0};
// mp in [NK, NKP) -> zeros (fourier tiling padding).
// ============================================================================
__global__ void k_prep() {
    int i = blockIdx.x * blockDim.x + threadIdx.x;
    if (i >= NKP * NB) return;
    int mp = i >> 4, b = i & 15;
    float2 v = make_float2(0.0f, 0.0f);
    if (mp == 0) {
        v = make_float2(g_gsum[b * MM], 0.0f);
    } else if (mp < NK) {
        float a = g_gsum[b * MM + mp];
        float c = g_gsum[b * MM + 2049 - mp];
        v = make_float2(a + c, a - c);
    }
    g_t2[mp * NB + b] = v;
}

// ============================================================================
// K_fourier: grid (129 k-octets, 10 mp-chunks of 104). Warp = one k.
// Lane = (par 0..3) x (slot 0..7): parity over mp (stride 4), slot = 2 batches.
// Per iter: LDG.128 + broadcast LDS.64 + 4 FFMA + 3 ALU -> 26 iterations.
// ============================================================================
__global__ __launch_bounds__(256) void k_fourier() {
    __shared__ float2 scs[MM];
    for (int i = threadIdx.x; i < MM; i += 256) scs[i] = g_cs[i];
    __syncthreads();

    int w    = threadIdx.x >> 5;
    int lane = threadIdx.x & 31;
    int k    = blockIdx.x * 8 + w;
    int y    = blockIdx.y;
    if (k >= NK) return;

    int par = lane >> 3;            // 0..3
    int s   = lane & 7;             // batch slot: batches 2s, 2s+1
    int mp0 = y * CHL + par;

    int t   = (int)(((long long)k * mp0) % MM);
    int stp = (4 * k) % MM;
    const float4* gt = (const float4*)(g_t2 + mp0 * NB) + s;

    float C0 = 0.f, S0 = 0.f, C1 = 0.f, S1 = 0.f;
    #pragma unroll
    for (int it = 0; it < 26; ++it) {       // covers mp0 + 4*it, 26*4 = 104 = CHL
        float2 cs = scs[t];
        float4 g  = __ldg(gt);
        C0 = fmaf(g.x, cs.x, C0);
        S0 = fmaf(g.y, cs.y, S0);
        C1 = fmaf(g.z, cs.x, C1);
        S1 = fmaf(g.w, cs.y, S1);
        gt += 32;                           // 4 mp rows x 8 float4
        t += stp; if (t >= MM) t -= MM;
    }
    // sum over the 4 parities (lanes with same slot s)
    #pragma unroll
    for (int o = 8; o <= 16; o <<= 1) {
        C0 += __shfl_xor_sync(0xffffffffu, C0, o);
        S0 += __shfl_xor_sync(0xffffffffu, S0, o);
        C1 += __shfl_xor_sync(0xffffffffu, C1, o);
        S1 += __shfl_xor_sync(0xffffffffu, S1, o);
    }
    if (lane < 8) {
        float4 val = make_float4(C0, S0, C1, S1);
        *(((float4*)(g_pF + (y * NK + k) * NB)) + s) = val;
    }
}

// ============================================================================
// K_comb: combine fourier chunk partials, fold D, write A (k-paired) + A0.
// ============================================================================
__global__ void k_comb() {
    int i = blockIdx.x * blockDim.x + threadIdx.x;
    if (i >= NK * NB) return;
    int k = i >> 4, b = i & 15;
    float C = 0.0f, S = 0.0f;
    #pragma unroll
    for (int y = 0; y < NCH; ++y) {
        float2 p = g_pF[(y * NK + k) * NB + b];
        C += p.x; S += p.y;
    }
    float re =  C;
    float im = -S;
    float D0 = g_D[k], D1 = g_D[NK + k];
    int j0 = 2 * b, j1 = 2 * b + 1;
    if (k == 0) {
        g_A0[j0] = D0 * re;
        g_A0[j1] = D1 * re;
    } else {
        int p    = (k - 1) >> 1;
        int comp = (k - 1) & 1;
        g_A4[(p * NJ + j0) * 2 + comp] = make_float2(D0 * re, D0 * im);
        g_A4[(p * NJ + j1) * 2 + comp] = make_float2(D1 * re, D1 * im);
    }
}

// ============================================================================
// K_synth: grid (65 mp-16-tiles, 16 k-slices of 32 pairs). Warp = 2 mp
// sharing each A float4; lane = j. Doubled trig table kills half the index
// chains: scs2[t + mp] needs no wrap.
// ============================================================================
__global__ __launch_bounds__(256) void k_synth() {
    __shared__ float2 scs[2 * MM];
    for (int i = threadIdx.x; i < MM; i += 256) {
        float2 v = g_cs[i];
        scs[i] = v;
        scs[i + MM] = v;
    }
    __syncthreads();

    int w    = threadIdx.x >> 5;
    int lane = threadIdx.x & 31;        // = j
    int e    = blockIdx.y;              // 0..15
    int mpA  = blockIdx.x * 16 + 2 * w;
    int mpB  = mpA + 1;
    if (mpA >= NK) return;
    bool vB = (mpB < NK);

    int p0 = e * 32;                    // pairs p0..p0+31, k = 2p+1, 2p+2
    int k0 = 2 * p0 + 1;

    int tA = (int)(((long long)mpA * k0) % MM);
    int sA = (2 * mpA) % MM;
    int tB = (int)(((long long)mpB * k0) % MM);
    int sB = (2 * mpB) % MM;

    const float4* ap = (const float4*)g_A4 + p0 * NJ + lane;

    float UA = 0.f, VA = 0.f, UB = 0.f, VB = 0.f;
    #pragma unroll 4
    for (int it = 0; it < 32; ++it) {
        float4 a = __ldg(ap);
        float2 cA0 = scs[tA], cA1 = scs[tA + mpA];
        UA = fmaf(a.x, cA0.x, UA);
        VA = fmaf(a.y, cA0.y, VA);
        UA = fmaf(a.z, cA1.x, UA);
        VA = fmaf(a.w, cA1.y, VA);
        if (vB) {
            float2 cB0 = scs[tB], cB1 = scs[tB + mpB];
            UB = fmaf(a.x, cB0.x, UB);
            VB = fmaf(a.y, cB0.y, VB);
            UB = fmaf(a.z, cB1.x, UB);
            VB = fmaf(a.w, cB1.y, VB);
        }
        ap += NJ;
        tA += sA; if (tA >= MM) tA -= MM;
        tB += sB; if (tB >= MM) tB -= MM;
    }
    g_pUV[(e * NK + mpA) * NJ + lane] = make_float2(UA, VA);
    if (vB)
        g_pUV[(e * NK + mpB) * NJ + lane] = make_float2(UB, VB);
}

// ============================================================================
// K_hcomb: combine synth partials, build packed H.
// H[mp]=(A0+2(U-V))/M, H[M-mp]=(A0+2(U+V))/M.
// ============================================================================
__global__ void k_hcomb() {
    int i = blockIdx.x * blockDim.x + threadIdx.x;
    if (i >= NK * NB) return;
    int mp = i >> 4, b = i & 15;
    int j0 = 2 * b, j1 = 2 * b + 1;
    float U0 = 0.f, V0 = 0.f, U1 = 0.f, V1 = 0.f;
    #pragma unroll
    for (int e = 0; e < NE; ++e) {
        float2 p0 = g_pUV[(e * NK + mp) * NJ + j0];
        float2 p1 = g_pUV[(e * NK + mp) * NJ + j1];
        U0 += p0.x; V0 += p0.y;
        U1 += p1.x; V1 += p1.y;
    }
    const float inv = 1.0f / 2049.0f;
    float a00 = g_A0[j0], a01 = g_A0[j1];
    float2 hm = make_float2((a00 + 2.0f * (U0 - V0)) * inv,
                            (a01 + 2.0f * (U1 - V1)) * inv);
    g_H[b * MM + mp] = hm;
    if (mp) {
        float2 hp = make_float2((a00 + 2.0f * (U0 + V0)) * inv,
                                (a01 + 2.0f * (U1 + V1)) * inv);
        g_H[b * MM + 2049 - mp] = hp;
    }
}

// ============================================================================
// K_out: fmm[b,n,c] = (1/M) * sum_{m in window} g[b,n,m] * H[b][m].c
// ============================================================================
__global__ __launch_bounds__(256) void k_out(const float* __restrict__ x,
                                             float* __restrict__ out) {
    int gid = blockIdx.x * blockDim.x + threadIdx.x;
    if (gid >= NB * NPT) return;
    int b = gid / NPT;

    float xs = __fmul_rn(x[gid], C2PL_F);
    int cen = __float2int_rn(xs * (float)(2049.0 / (2.0 * M_PI)));

    const float2* Hb = g_H + b * MM;

    double a0 = 0.0, a1 = 0.0;
    #pragma unroll 4
    for (int j = -WJ; j <= WJ; ++j) {
        int m = cen + j;
        if (m < 0 || m >= MM) continue;
        float d = __fsub_rn(xs, g_xg[m]);
        if (fabsf(d) < WIN_R) {
            float arg = __fdiv_rn(__fmul_rn(d, d), FT32_F);
            double gv = (double)expf(-arg);
            float2 h = Hb[m];
            a0 = fma(gv, (double)h.x, a0);
            a1 = fma(gv, (double)h.y, a1);
        }
    }
    out[gid * 2 + 0] = (float)(a0 / 2049.0);
    out[gid * 2 + 1] = (float)(a1 / 2049.0);
}

// ============================================================================
extern "C" void kernel_launch(void* const* d_in, const int* in_sizes, int n_in,
                              void* d_out, int out_size) {
    const float* x   = (const float*)d_in[0];
    const float* sh0 = (const float*)d_in[1];
    const float* am0 = (const float*)d_in[2];
    const float* sh1 = (const float*)d_in[3];
    const float* am1 = (const float*)d_in[4];
    float* out = (float*)d_out;

    k_init<<<(MM + 255) / 256, 256>>>(sh0, am0, sh1, am1);

    dim3 gsp(NB, 17);
    k_spread<<<gsp, 128>>>(x);

    k_prep<<<(NKP * NB + 255) / 256, 256>>>();

    dim3 gf(129, NCH);                  // 8 k per block x 10 mp-chunks
    k_fourier<<<gf, 256>>>();
    k_comb<<<(NK * NB + 255) / 256, 256>>>();

    dim3 gsy(65, NE);                   // 16 mp per block x 16 k-slices
    k_synth<<<gsy, 256>>>();
    k_hcomb<<<(NK * NB + 255) / 256, 256>>>();

    k_out<<<(NB * NPT + 255) / 256, 256>>>(x, out);
}

// round 14
// speedup vs baseline: 1.5466x; 1.0419x over previous
#include <cuda_runtime.h>
#include <math.h>

#define MM    2049        // mesh points
#define NK    1025        // kappa = 0..1024 (Hermitian half)
#define NKP   1040        // padded mp count for fourier tiling
#define NB    16          // batch
#define NPT   1024        // points per batch
#define NJ    32          // (b,c) pairs: j = b*2 + c
#define NP4   512         // k-pairs (k=1..1024 -> 512 pairs)
#define NCH   10          // fourier mp-chunks
#define CHL   104         // chunk length (10 x 104 = 1040)
#define NE    16          // synth k-slices (16 x 32 pairs = 512)

// ---- f32-faithful constants ----
#define C2PL_F   ((float)(2.0 * M_PI / 10.0))          // 2*pi/L as f32
#define FT32_F   ((float)(4.0 * 2.821e-5))             // 4*tau as f32
#define INV4T_F  (1.0f / FT32_F)                        // reciprocal (<=1ulp arg diff)
#define WIN_R    0.1090f                                // support radius (rad)
#define WJ       39                                     // window half-width in bins

// ---- scratch (device globals; no allocation allowed) ----
__device__ float  g_gsum[NB * MM];
__device__ float2 g_t2 [NKP * NB];       // [mp][b] = {gp, gm}, zero-padded
__device__ float2 g_pF [NCH * NK * NB];  // fourier partials {C, S}
__device__ float2 g_A4 [NP4 * NJ * 2];   // [(p*32+j)*2+comp] = {Are, Aim}, k=2p+1+comp
__device__ float  g_A0 [NJ];             // k = 0 term (D*F0)
__device__ float2 g_pUV[NE * NK * NJ];   // synth partials {U, V}
__device__ float2 g_H  [NB * MM];        // H packed {c0, c1} per (b, m)
__device__ float  g_D  [2  * NK];
__device__ float2 g_cs [MM];             // {cos, sin}(2*pi*i/M)
__device__ float  g_xg [MM];

// XGRID exactly as numpy: v = i*(10/2049); xg = (2*pi*v)/10, f64 then cast f32
__device__ __forceinline__ float xgrid_f32(int m) {
    double v = (double)m * (10.0 / 2049.0);
    v = (6.283185307179586 * v) / 10.0;
    return (float)v;
}

// ============================================================================
// K_init: trig table, xgrid, Fourier multipliers D_c(kappa)
// 64-thread blocks -> 33 blocks spread the f64 sincos across more SMs.
// ============================================================================
__global__ __launch_bounds__(64) void k_init(
        const float* __restrict__ sh0, const float* __restrict__ am0,
        const float* __restrict__ sh1, const float* __restrict__ am1) {
    int i = blockIdx.x * 64 + threadIdx.x;
    if (i < MM) {
        double th = (6.283185307179586 * (double)i) / 2049.0;
        double s, c;
        sincos(th, &s, &c);
        g_cs[i] = make_float2((float)c, (float)s);
        g_xg[i] = xgrid_f32(i);
    }
    if (i < NK) {
        double tau = (double)((float)2.821e-5);
        double k2  = (double)i * (double)i;
        double dec2 = (M_PI / tau) * exp(2.0 * k2 * tau); // deconv^2
        double lo2p = 10.0 / (2.0 * M_PI);                // L/(2*pi)
        double s0 = 5.0 * (double)sh0[0];
        double s1 = 5.0 * (double)sh1[0];
        double m1 = -(double)am0[0] * 4.0 * M_PI / (k2 + s0 * s0);
        double den = k2 + s1 * s1;
        double m2 =  (double)am1[0] * 4.0 * M_PI / (den * den);
        g_D[i]      = (float)(lo2p * dec2 * m1);
        g_D[NK + i] = (float)(lo2p * dec2 * m2);
    }
}

// ============================================================================
// K_spread: gsum[b][m] = sum_n __expf(-((x_n*c - xg_m)^2)*inv(4 tau))
// Coalesced point loads; deterministic candidate compaction; cheap exp.
// ============================================================================
__global__ __launch_bounds__(128) void k_spread(const float* __restrict__ x) {
    __shared__ float cand[NPT];
    __shared__ int   warp_cnt[4];

    int b    = blockIdx.x;
    int tile = blockIdx.y;          // 0..16
    int lo   = tile * 128;
    int t    = threadIdx.x;
    int lane = t & 31, w = t >> 5;

    const float* xb = x + b * NPT;
    float v[8];
    int flags = 0, cnt = 0;
    float fl = (float)(lo - 40), fh = (float)(lo + 127 + 40);
    #pragma unroll
    for (int i = 0; i < 8; ++i) {
        float xs = __fmul_rn(xb[i * 128 + t], C2PL_F);   // coalesced
        v[i] = xs;
        float cenf = xs * (float)(2049.0 / (2.0 * M_PI));
        int ok = (cenf >= fl) && (cenf <= fh);
        flags |= ok << i;
        cnt += ok;
    }
    int inc = cnt;
    #pragma unroll
    for (int o = 1; o < 32; o <<= 1) {
        int z = __shfl_up_sync(0xffffffffu, inc, o);
        if (lane >= o) inc += z;
    }
    if (lane == 31) warp_cnt[w] = inc;
    __syncthreads();
    int woff = 0;
    for (int i = 0; i < w; ++i) woff += warp_cnt[i];
    int ntot = warp_cnt[0] + warp_cnt[1] + warp_cnt[2] + warp_cnt[3];
    int off = woff + inc - cnt;
    #pragma unroll
    for (int i = 0; i < 8; ++i)
        if ((flags >> i) & 1) cand[off++] = v[i];
    __syncthreads();

    int m = lo + t;
    if (m < MM) {
        float xg = g_xg[m];
        float acc = 0.0f;
        for (int i = 0; i < ntot; ++i) {
            float d = __fsub_rn(cand[i], xg);
            if (fabsf(d) < WIN_R) {
                float arg = __fmul_rn(__fmul_rn(d, d), INV4T_F);
                acc += __expf(-arg);
            }
        }
        g_gsum[b * MM + m] = acc;
    }
}

// ============================================================================
// K_prep: g_t2[mp][b] = {g[mp]+g[M-mp], g[mp]-g[M-mp]}; mp=0 -> {g[0],0};
// mp in [NK, NKP) -> zeros (fourier tiling padding).
// ============================================================================
__global__ void k_prep() {
    int i = blockIdx.x * blockDim.x + threadIdx.x;
    if (i >= NKP * NB) return;
    int mp = i >> 4, b = i & 15;
    float2 v = make_float2(0.0f, 0.0f);
    if (mp == 0) {
        v = make_float2(g_gsum[b * MM], 0.0f);
    } else if (mp < NK) {
        float a = g_gsum[b * MM + mp];
        float c = g_gsum[b * MM + 2049 - mp];
        v = make_float2(a + c, a - c);
    }
    g_t2[mp * NB + b] = v;
}

// ============================================================================
// K_fourier: grid (129 k-octets, 10 mp-chunks of 104). Warp = one k.
// Lane = (par 0..7) x (slot 0..3): parity over mp (stride 8), slot = 4 batches.
// Per iter: 2 LDG.128 + 1 broadcast LDS.64 + 8 FFMA + 3 ALU -> 13 iterations.
// ============================================================================
__global__ __launch_bounds__(256) void k_fourier() {
    __shared__ float2 scs[MM];
    for (int i = threadIdx.x; i < MM; i += 256) scs[i] = g_cs[i];
    __syncthreads();

    int w    = threadIdx.x >> 5;
    int lane = threadIdx.x & 31;
    int k    = blockIdx.x * 8 + w;
    int y    = blockIdx.y;
    if (k >= NK) return;

    int par = lane >> 2;            // 0..7
    int s   = lane & 3;             // batch slot: batches 4s..4s+3
    int mp0 = y * CHL + par;

    int t   = (k * mp0) % MM;
    int stp = (8 * k) % MM;
    const float4* gt0 = (const float4*)(g_t2 + mp0 * NB) + 2 * s;

    float c0 = 0.f, s0 = 0.f, c1 = 0.f, s1 = 0.f;
    float c2 = 0.f, s2 = 0.f, c3 = 0.f, s3 = 0.f;
    #pragma unroll
    for (int it = 0; it < 13; ++it) {       // mp0 + 8*it, 13*8 = 104 = CHL
        float2 cs = scs[t];
        float4 ga = __ldg(gt0 + it * 64);       // batches 4s, 4s+1
        float4 gb = __ldg(gt0 + it * 64 + 1);   // batches 4s+2, 4s+3
        c0 = fmaf(ga.x, cs.x, c0);
        s0 = fmaf(ga.y, cs.y, s0);
        c1 = fmaf(ga.z, cs.x, c1);
        s1 = fmaf(ga.w, cs.y, s1);
        c2 = fmaf(gb.x, cs.x, c2);
        s2 = fmaf(gb.y, cs.y, s2);
        c3 = fmaf(gb.z, cs.x, c3);
        s3 = fmaf(gb.w, cs.y, s3);
        t += stp; if (t >= MM) t -= MM;
    }
    // sum over the 8 parities (lanes with same slot s)
    #pragma unroll
    for (int o = 4; o <= 16; o <<= 1) {
        c0 += __shfl_xor_sync(0xffffffffu, c0, o);
        s0 += __shfl_xor_sync(0xffffffffu, s0, o);
        c1 += __shfl_xor_sync(0xffffffffu, c1, o);
        s1 += __shfl_xor_sync(0xffffffffu, s1, o);
        c2 += __shfl_xor_sync(0xffffffffu, c2, o);
        s2 += __shfl_xor_sync(0xffffffffu, s2, o);
        c3 += __shfl_xor_sync(0xffffffffu, c3, o);
        s3 += __shfl_xor_sync(0xffffffffu, s3, o);
    }
    if (lane < 4) {                 // par == 0, one lane per slot
        float4* dst = (float4*)(g_pF + (y * NK + k) * NB) + 2 * s;
        dst[0] = make_float4(c0, s0, c1, s1);
        dst[1] = make_float4(c2, s2, c3, s3);
    }
}

// ============================================================================
// K_comb: combine fourier chunk partials, fold D, write A (k-paired) + A0.
// ============================================================================
__global__ void k_comb() {
    int i = blockIdx.x * blockDim.x + threadIdx.x;
    if (i >= NK * NB) return;
    int k = i >> 4, b = i & 15;
    float C = 0.0f, S = 0.0f;
    #pragma unroll
    for (int y = 0; y < NCH; ++y) {
        float2 p = g_pF[(y * NK + k) * NB + b];
        C += p.x; S += p.y;
    }
    float re =  C;
    float im = -S;
    float D0 = g_D[k], D1 = g_D[NK + k];
    int j0 = 2 * b, j1 = 2 * b + 1;
    if (k == 0) {
        g_A0[j0] = D0 * re;
        g_A0[j1] = D1 * re;
    } else {
        int p    = (k - 1) >> 1;
        int comp = (k - 1) & 1;
        g_A4[(p * NJ + j0) * 2 + comp] = make_float2(D0 * re, D0 * im);
        g_A4[(p * NJ + j1) * 2 + comp] = make_float2(D1 * re, D1 * im);
    }
}

// ============================================================================
// K_synth: grid (65 mp-16-tiles, 16 k-slices of 32 pairs). Warp = 2 mp
// sharing each A float4; lane = j. Doubled trig table halves the index chains.
// ============================================================================
__global__ __launch_bounds__(256) void k_synth() {
    __shared__ float2 scs[2 * MM];
    for (int i = threadIdx.x; i < MM; i += 256) {
        float2 v = g_cs[i];
        scs[i] = v;
        scs[i + MM] = v;
    }
    __syncthreads();

    int w    = threadIdx.x >> 5;
    int lane = threadIdx.x & 31;        // = j
    int e    = blockIdx.y;              // 0..15
    int mpA  = blockIdx.x * 16 + 2 * w;
    int mpB  = mpA + 1;
    if (mpA >= NK) return;
    bool vB = (mpB < NK);

    int p0 = e * 32;                    // pairs p0..p0+31, k = 2p+1, 2p+2
    int k0 = 2 * p0 + 1;

    int tA = (int)(((long long)mpA * k0) % MM);
    int sA = (2 * mpA) % MM;
    int tB = (int)(((long long)mpB * k0) % MM);
    int sB = (2 * mpB) % MM;

    const float4* ap = (const float4*)g_A4 + p0 * NJ + lane;

    float UA = 0.f, VA = 0.f, UB = 0.f, VB = 0.f;
    #pragma unroll 4
    for (int it = 0; it < 32; ++it) {
        float4 a = __ldg(ap);
        float2 cA0 = scs[tA], cA1 = scs[tA + mpA];
        UA = fmaf(a.x, cA0.x, UA);
        VA = fmaf(a.y, cA0.y, VA);
        UA = fmaf(a.z, cA1.x, UA);
        VA = fmaf(a.w, cA1.y, VA);
        if (vB) {
            float2 cB0 = scs[tB], cB1 = scs[tB + mpB];
            UB = fmaf(a.x, cB0.x, UB);
            VB = fmaf(a.y, cB0.y, VB);
            UB = fmaf(a.z, cB1.x, UB);
            VB = fmaf(a.w, cB1.y, VB);
        }
        ap += NJ;
        tA += sA; if (tA >= MM) tA -= MM;
        tB += sB; if (tB >= MM) tB -= MM;
    }
    g_pUV[(e * NK + mpA) * NJ + lane] = make_float2(UA, VA);
    if (vB)
        g_pUV[(e * NK + mpB) * NJ + lane] = make_float2(UB, VB);
}

// ============================================================================
// K_hcomb: combine synth partials, build packed H.
// H[mp]=(A0+2(U-V))/M, H[M-mp]=(A0+2(U+V))/M.
// ============================================================================
__global__ void k_hcomb() {
    int i = blockIdx.x * blockDim.x + threadIdx.x;
    if (i >= NK * NB) return;
    int mp = i >> 4, b = i & 15;
    int j0 = 2 * b, j1 = 2 * b + 1;
    float U0 = 0.f, V0 = 0.f, U1 = 0.f, V1 = 0.f;
    #pragma unroll
    for (int e = 0; e < NE; ++e) {
        float2 p0 = g_pUV[(e * NK + mp) * NJ + j0];
        float2 p1 = g_pUV[(e * NK + mp) * NJ + j1];
        U0 += p0.x; V0 += p0.y;
        U1 += p1.x; V1 += p1.y;
    }
    const float inv = 1.0f / 2049.0f;
    float a00 = g_A0[j0], a01 = g_A0[j1];
    float2 hm = make_float2((a00 + 2.0f * (U0 - V0)) * inv,
                            (a01 + 2.0f * (U1 - V1)) * inv);
    g_H[b * MM + mp] = hm;
    if (mp) {
        float2 hp = make_float2((a00 + 2.0f * (U0 + V0)) * inv,
                                (a01 + 2.0f * (U1 + V1)) * inv);
        g_H[b * MM + 2049 - mp] = hp;
    }
}

// ============================================================================
// K_out: fmm[b,n,c] = (1/M) * sum_{m in window} g[b,n,m] * H[b][m].c
// Cheap exp; f64 accumulator (2.5M DFMA, ~0.5us).
// ============================================================================
__global__ __launch_bounds__(256) void k_out(const float* __restrict__ x,
                                             float* __restrict__ out) {
    int gid = blockIdx.x * blockDim.x + threadIdx.x;
    if (gid >= NB * NPT) return;
    int b = gid / NPT;

    float xs = __fmul_rn(x[gid], C2PL_F);
    int cen = __float2int_rn(xs * (float)(2049.0 / (2.0 * M_PI)));

    const float2* Hb = g_H + b * MM;

    double a0 = 0.0, a1 = 0.0;
    #pragma unroll 4
    for (int j = -WJ; j <= WJ; ++j) {
        int m = cen + j;
        if (m < 0 || m >= MM) continue;
        float d = __fsub_rn(xs, g_xg[m]);
        if (fabsf(d) < WIN_R) {
            float arg = __fmul_rn(__fmul_rn(d, d), INV4T_F);
            double gv = (double)__expf(-arg);
            float2 h = Hb[m];
            a0 = fma(gv, (double)h.x, a0);
            a1 = fma(gv, (double)h.y, a1);
        }
    }
    out[gid * 2 + 0] = (float)(a0 / 2049.0);
    out[gid * 2 + 1] = (float)(a1 / 2049.0);
}

// ============================================================================
extern "C" void kernel_launch(void* const* d_in, const int* in_sizes, int n_in,
                              void* d_out, int out_size) {
    const float* x   = (const float*)d_in[0];
    const float* sh0 = (const float*)d_in[1];
    const float* am0 = (const float*)d_in[2];
    const float* sh1 = (const float*)d_in[3];
    const float* am1 = (const float*)d_in[4];
    float* out = (float*)d_out;

    k_init<<<(MM + 63) / 64, 64>>>(sh0, am0, sh1, am1);

    dim3 gsp(NB, 17);
    k_spread<<<gsp, 128>>>(x);

    k_prep<<<(NKP * NB + 255) / 256, 256>>>();

    dim3 gf(129, NCH);                  // 8 k per block x 10 mp-chunks
    k_fourier<<<gf, 256>>>();
    k_comb<<<(NK * NB + 255) / 256, 256>>>();

    dim3 gsy(65, NE);                   // 16 mp per block x 16 k-slices
    k_synth<<<gsy, 256>>>();
    k_hcomb<<<(NK * NB + 255) / 256, 256>>>();

    k_out<<<(NB * NPT + 255) / 256, 256>>>(x, out);
}

// round 16
// speedup vs baseline: 1.5766x; 1.0194x over previous
#include <cuda_runtime.h>
#include <math.h>

#define MM    2049        // mesh points
#define NK    1025        // kappa = 0..1024 (Hermitian half)
#define NB    16          // batch
#define NPT   1024        // points per batch
#define NJ    32          // (b,c) pairs: j = b*2 + c
#define NP4   512         // k-pairs (k=1..1024 -> 512 pairs)
#define NCH   10          // fourier mp-chunks
#define CHL   104         // chunk length (10 x 104 = 1040, zero-padded past 1024)
#define TPAD  18          // padded float2 row stride for st2 (conflict-free)
#define NE    16          // synth k-slices (16 x 32 pairs = 512)

// ---- f32-faithful constants ----
#define C2PL_F   ((float)(2.0 * M_PI / 10.0))          // 2*pi/L as f32
#define FT32_F   ((float)(4.0 * 2.821e-5))             // 4*tau as f32
#define INV4T_F  (1.0f / FT32_F)                        // reciprocal (<=1ulp arg diff)
#define WIN_R    0.1090f                                // support radius (rad)
#define WJ       39                                     // window half-width in bins

// ---- scratch (device globals; no allocation allowed) ----
__device__ float  g_gsum[NB * MM];
__device__ float2 g_pF [NCH * NK * NB];  // fourier partials {C, S}
__device__ float2 g_A4 [NP4 * NJ * 2];   // [(p*32+j)*2+comp] = {Are, Aim}, k=2p+1+comp
__device__ float  g_A0 [NJ];             // k = 0 term (D*F0)
__device__ float2 g_pUV[NE * NK * NJ];   // synth partials {U, V}
__device__ float2 g_H  [NB * MM];        // H packed {c0, c1} per (b, m)
__device__ float  g_D  [2  * NK];
__device__ float2 g_cs [MM];             // {cos, sin}(2*pi*i/M)
__device__ float  g_xg [MM];

// XGRID exactly as numpy: v = i*(10/2049); xg = (2*pi*v)/10, f64 then cast f32
__device__ __forceinline__ float xgrid_f32(int m) {
    double v = (double)m * (10.0 / 2049.0);
    v = (6.283185307179586 * v) / 10.0;
    return (float)v;
}

// ============================================================================
// K_init: trig table, xgrid, Fourier multipliers D_c(kappa)
// ============================================================================
__global__ __launch_bounds__(64) void k_init(
        const float* __restrict__ sh0, const float* __restrict__ am0,
        const float* __restrict__ sh1, const float* __restrict__ am1) {
    int i = blockIdx.x * 64 + threadIdx.x;
    if (i < MM) {
        double th = (6.283185307179586 * (double)i) / 2049.0;
        double s, c;
        sincos(th, &s, &c);
        g_cs[i] = make_float2((float)c, (float)s);
        g_xg[i] = xgrid_f32(i);
    }
    if (i < NK) {
        double tau = (double)((float)2.821e-5);
        double k2  = (double)i * (double)i;
        double dec2 = (M_PI / tau) * exp(2.0 * k2 * tau); // deconv^2
        double lo2p = 10.0 / (2.0 * M_PI);                // L/(2*pi)
        double s0 = 5.0 * (double)sh0[0];
        double s1 = 5.0 * (double)sh1[0];
        double m1 = -(double)am0[0] * 4.0 * M_PI / (k2 + s0 * s0);
        double den = k2 + s1 * s1;
        double m2 =  (double)am1[0] * 4.0 * M_PI / (den * den);
        g_D[i]      = (float)(lo2p * dec2 * m1);
        g_D[NK + i] = (float)(lo2p * dec2 * m2);
    }
}

// ============================================================================
// K_spread: gsum[b][m] = sum_n __expf(-((x_n*c - xg_m)^2)*inv(4 tau))
// ============================================================================
__global__ __launch_bounds__(128) void k_spread(const float* __restrict__ x) {
    __shared__ float cand[NPT];
    __shared__ int   warp_cnt[4];

    int b    = blockIdx.x;
    int tile = blockIdx.y;          // 0..16
    int lo   = tile * 128;
    int t    = threadIdx.x;
    int lane = t & 31, w = t >> 5;

    const float* xb = x + b * NPT;
    float v[8];
    int flags = 0, cnt = 0;
    float fl = (float)(lo - 40), fh = (float)(lo + 127 + 40);
    #pragma unroll
    for (int i = 0; i < 8; ++i) {
        float xs = __fmul_rn(xb[i * 128 + t], C2PL_F);   // coalesced
        v[i] = xs;
        float cenf = xs * (float)(2049.0 / (2.0 * M_PI));
        int ok = (cenf >= fl) && (cenf <= fh);
        flags |= ok << i;
        cnt += ok;
    }
    int inc = cnt;
    #pragma unroll
    for (int o = 1; o < 32; o <<= 1) {
        int z = __shfl_up_sync(0xffffffffu, inc, o);
        if (lane >= o) inc += z;
    }
    if (lane == 31) warp_cnt[w] = inc;
    __syncthreads();
    int woff = 0;
    for (int i = 0; i < w; ++i) woff += warp_cnt[i];
    int ntot = warp_cnt[0] + warp_cnt[1] + warp_cnt[2] + warp_cnt[3];
    int off = woff + inc - cnt;
    #pragma unroll
    for (int i = 0; i < 8; ++i)
        if ((flags >> i) & 1) cand[off++] = v[i];
    __syncthreads();

    int m = lo + t;
    if (m < MM) {
        float xg = g_xg[m];
        float acc = 0.0f;
        for (int i = 0; i < ntot; ++i) {
            float d = __fsub_rn(cand[i], xg);
            if (fabsf(d) < WIN_R) {
                float arg = __fmul_rn(__fmul_rn(d, d), INV4T_F);
                acc += __expf(-arg);
            }
        }
        g_gsum[b * MM + m] = acc;
    }
}

// ============================================================================
// K_fourier (prep fused): block stages trig (16.4KB) + computes its own
// sum/diff chunk st2 (104 x 16, stride-18 float2 rows) from g_gsum.
// st2 MUST be 16B-aligned: inner loop reads it via LDS.128.
// Warp = one k; lane = (par 0..7) x (slot 0..3).
// ============================================================================
__global__ __launch_bounds__(256) void k_fourier() {
    __shared__ __align__(16) float2 scs[MM];           // 16392 B
    __shared__ __align__(16) float2 st2[CHL * TPAD];   // 14976 B

    int y = blockIdx.y;

    for (int i = threadIdx.x; i < MM; i += 256) scs[i] = g_cs[i];
    // fused prep: st2[mpl][b] = {g[mp]+g[M-mp], g[mp]-g[M-mp]}
    for (int e = threadIdx.x; e < CHL * NB; e += 256) {
        int b   = e / CHL;                  // consecutive e -> consecutive mpl (coalesced gsum)
        int mpl = e - b * CHL;
        int mp  = y * CHL + mpl;
        float2 v = make_float2(0.0f, 0.0f);
        if (mp == 0) {
            v = make_float2(g_gsum[b * MM], 0.0f);
        } else if (mp < NK) {
            float a = g_gsum[b * MM + mp];
            float c = g_gsum[b * MM + 2049 - mp];
            v = make_float2(a + c, a - c);
        }
        st2[mpl * TPAD + b] = v;
    }
    __syncthreads();

    int w    = threadIdx.x >> 5;
    int lane = threadIdx.x & 31;
    int k    = blockIdx.x * 8 + w;
    if (k >= NK) return;

    int par = lane >> 2;            // 0..7  (mp parity, stride 8)
    int s   = lane & 3;             // batch slot: batches 4s..4s+3
    int mp0 = y * CHL + par;

    int t   = (k * mp0) % MM;
    int stp = (8 * k) % MM;
    const float2* row = st2 + par * TPAD + s * 4;   // element index even -> 16B-aligned

    float c0 = 0.f, s0 = 0.f, c1 = 0.f, s1 = 0.f;
    float c2 = 0.f, s2 = 0.f, c3 = 0.f, s3 = 0.f;
    #pragma unroll
    for (int it = 0; it < 13; ++it) {       // mp0 + 8*it, 13*8 = 104 = CHL
        float2 cs = scs[t];
        const float4* p = (const float4*)(row + it * (8 * TPAD));
        float4 ga = p[0];                   // batches 4s, 4s+1
        float4 gb = p[1];                   // batches 4s+2, 4s+3
        c0 = fmaf(ga.x, cs.x, c0);
        s0 = fmaf(ga.y, cs.y, s0);
        c1 = fmaf(ga.z, cs.x, c1);
        s1 = fmaf(ga.w, cs.y, s1);
        c2 = fmaf(gb.x, cs.x, c2);
        s2 = fmaf(gb.y, cs.y, s2);
        c3 = fmaf(gb.z, cs.x, c3);
        s3 = fmaf(gb.w, cs.y, s3);
        t += stp; if (t >= MM) t -= MM;
    }
    // sum over the 8 parities (lanes with same slot s)
    #pragma unroll
    for (int o = 4; o <= 16; o <<= 1) {
        c0 += __shfl_xor_sync(0xffffffffu, c0, o);
        s0 += __shfl_xor_sync(0xffffffffu, s0, o);
        c1 += __shfl_xor_sync(0xffffffffu, c1, o);
        s1 += __shfl_xor_sync(0xffffffffu, s1, o);
        c2 += __shfl_xor_sync(0xffffffffu, c2, o);
        s2 += __shfl_xor_sync(0xffffffffu, s2, o);
        c3 += __shfl_xor_sync(0xffffffffu, c3, o);
        s3 += __shfl_xor_sync(0xffffffffu, s3, o);
    }
    if (lane < 4) {                 // par == 0, one lane per slot
        float4* dst = (float4*)(g_pF + (y * NK + k) * NB) + 2 * s;
        dst[0] = make_float4(c0, s0, c1, s1);
        dst[1] = make_float4(c2, s2, c3, s3);
    }
}

// ============================================================================
// K_comb: combine fourier chunk partials, fold D, write A (k-paired) + A0.
// ============================================================================
__global__ void k_comb() {
    int i = blockIdx.x * blockDim.x + threadIdx.x;
    if (i >= NK * NB) return;
    int k = i >> 4, b = i & 15;
    float C = 0.0f, S = 0.0f;
    #pragma unroll
    for (int y = 0; y < NCH; ++y) {
        float2 p = g_pF[(y * NK + k) * NB + b];
        C += p.x; S += p.y;
    }
    float re =  C;
    float im = -S;
    float D0 = g_D[k], D1 = g_D[NK + k];
    int j0 = 2 * b, j1 = 2 * b + 1;
    if (k == 0) {
        g_A0[j0] = D0 * re;
        g_A0[j1] = D1 * re;
    } else {
        int p    = (k - 1) >> 1;
        int comp = (k - 1) & 1;
        g_A4[(p * NJ + j0) * 2 + comp] = make_float2(D0 * re, D0 * im);
        g_A4[(p * NJ + j1) * 2 + comp] = make_float2(D1 * re, D1 * im);
    }
}

// ============================================================================
// K_synth: grid (65 mp-16-tiles, 16 k-slices of 32 pairs). Block stages its
// 16KB A-slab (shared by all 8 warps) into smem; warp = 2 mp, lane = j.
// ============================================================================
__global__ __launch_bounds__(256) void k_synth() {
    __shared__ __align__(16) float2 scs[MM];   // 16392 B
    __shared__ float4 sA[32 * NJ];             // 16384 B: [pair_local][j]

    int e = blockIdx.y;                     // k-slice 0..15
    int p0 = e * 32;                        // pairs p0..p0+31

    for (int i = threadIdx.x; i < MM; i += 256) scs[i] = g_cs[i];
    {
        const float4* src = (const float4*)g_A4 + p0 * NJ;
        for (int i = threadIdx.x; i < 32 * NJ; i += 256) sA[i] = src[i];
    }
    __syncthreads();

    int w    = threadIdx.x >> 5;
    int lane = threadIdx.x & 31;        // = j
    int mpA  = blockIdx.x * 16 + 2 * w;
    int mpB  = mpA + 1;
    if (mpA >= NK) return;
    bool vB = (mpB < NK);

    int k0 = 2 * p0 + 1;

    int tA  = (int)(((long long)mpA * k0) % MM);
    int tA2 = tA + mpA; if (tA2 >= MM) tA2 -= MM;
    int sAtp = (2 * mpA) % MM;
    int tB  = (int)(((long long)mpB * k0) % MM);
    int tB2 = tB + mpB; if (tB2 >= MM) tB2 -= MM;
    int sBtp = (2 * mpB) % MM;

    const float4* ap = sA + lane;

    float UA = 0.f, VA = 0.f, UB = 0.f, VB = 0.f;
    #pragma unroll 4
    for (int it = 0; it < 32; ++it) {
        float4 a = ap[it * NJ];
        float2 cA0 = scs[tA], cA1 = scs[tA2];
        UA = fmaf(a.x, cA0.x, UA);
        VA = fmaf(a.y, cA0.y, VA);
        UA = fmaf(a.z, cA1.x, UA);
        VA = fmaf(a.w, cA1.y, VA);
        if (vB) {
            float2 cB0 = scs[tB], cB1 = scs[tB2];
            UB = fmaf(a.x, cB0.x, UB);
            VB = fmaf(a.y, cB0.y, VB);
            UB = fmaf(a.z, cB1.x, UB);
            VB = fmaf(a.w, cB1.y, VB);
        }
        tA  += sAtp; if (tA  >= MM) tA  -= MM;
        tA2 += sAtp; if (tA2 >= MM) tA2 -= MM;
        tB  += sBtp; if (tB  >= MM) tB  -= MM;
        tB2 += sBtp; if (tB2 >= MM) tB2 -= MM;
    }
    g_pUV[(e * NK + mpA) * NJ + lane] = make_float2(UA, VA);
    if (vB)
        g_pUV[(e * NK + mpB) * NJ + lane] = make_float2(UB, VB);
}

// ============================================================================
// K_hcomb: combine synth partials, build packed H.
// H[mp]=(A0+2(U-V))/M, H[M-mp]=(A0+2(U+V))/M.
// ============================================================================
__global__ void k_hcomb() {
    int i = blockIdx.x * blockDim.x + threadIdx.x;
    if (i >= NK * NB) return;
    int mp = i >> 4, b = i & 15;
    int j0 = 2 * b, j1 = 2 * b + 1;
    float U0 = 0.f, V0 = 0.f, U1 = 0.f, V1 = 0.f;
    #pragma unroll
    for (int e = 0; e < NE; ++e) {
        float2 p0 = g_pUV[(e * NK + mp) * NJ + j0];
        float2 p1 = g_pUV[(e * NK + mp) * NJ + j1];
        U0 += p0.x; V0 += p0.y;
        U1 += p1.x; V1 += p1.y;
    }
    const float inv = 1.0f / 2049.0f;
    float a00 = g_A0[j0], a01 = g_A0[j1];
    float2 hm = make_float2((a00 + 2.0f * (U0 - V0)) * inv,
                            (a01 + 2.0f * (U1 - V1)) * inv);
    g_H[b * MM + mp] = hm;
    if (mp) {
        float2 hp = make_float2((a00 + 2.0f * (U0 + V0)) * inv,
                                (a01 + 2.0f * (U1 + V1)) * inv);
        g_H[b * MM + 2049 - mp] = hp;
    }
}

// ============================================================================
// K_out: fmm[b,n,c] = (1/M) * sum_{m in window} g[b,n,m] * H[b][m].c
// ============================================================================
__global__ __launch_bounds__(256) void k_out(const float* __restrict__ x,
                                             float* __restrict__ out) {
    int gid = blockIdx.x * blockDim.x + threadIdx.x;
    if (gid >= NB * NPT) return;
    int b = gid / NPT;

    float xs = __fmul_rn(x[gid], C2PL_F);
    int cen = __float2int_rn(xs * (float)(2049.0 / (2.0 * M_PI)));

    const float2* Hb = g_H + b * MM;

    double a0 = 0.0, a1 = 0.0;
    #pragma unroll 4
    for (int j = -WJ; j <= WJ; ++j) {
        int m = cen + j;
        if (m < 0 || m >= MM) continue;
        float d = __fsub_rn(xs, g_xg[m]);
        if (fabsf(d) < WIN_R) {
            float arg = __fmul_rn(__fmul_rn(d, d), INV4T_F);
            double gv = (double)__expf(-arg);
            float2 h = Hb[m];
            a0 = fma(gv, (double)h.x, a0);
            a1 = fma(gv, (double)h.y, a1);
        }
    }
    out[gid * 2 + 0] = (float)(a0 / 2049.0);
    out[gid * 2 + 1] = (float)(a1 / 2049.0);
}

// ============================================================================
extern "C" void kernel_launch(void* const* d_in, const int* in_sizes, int n_in,
                              void* d_out, int out_size) {
    const float* x   = (const float*)d_in[0];
    const float* sh0 = (const float*)d_in[1];
    const float* am0 = (const float*)d_in[2];
    const float* sh1 = (const float*)d_in[3];
    const float* am1 = (const float*)d_in[4];
    float* out = (float*)d_out;

    k_init<<<(MM + 63) / 64, 64>>>(sh0, am0, sh1, am1);

    dim3 gsp(NB, 17);
    k_spread<<<gsp, 128>>>(x);

    dim3 gf(129, NCH);                  // 8 k per block x 10 mp-chunks (prep fused)
    k_fourier<<<gf, 256>>>();
    k_comb<<<(NK * NB + 255) / 256, 256>>>();

    dim3 gsy(65, NE);                   // 16 mp per block x 16 k-slices
    k_synth<<<gsy, 256>>>();
    k_hcomb<<<(NK * NB + 255) / 256, 256>>>();

    k_out<<<(NB * NPT + 255) / 256, 256>>>(x, out);
}

// round 17
// speedup vs baseline: 1.8660x; 1.1836x over previous
#include <cuda_runtime.h>
#include <math.h>

#define MM    2049        // mesh points
#define NK    1025        // kappa = 0..1024 (Hermitian half)
#define NB    16          // batch
#define NPT   1024        // points per batch
#define NJ    32          // (b,c) pairs: j = b*2 + c
#define NP4   512         // k-pairs (k=1..1024 -> 512 pairs)
#define NCH   5           // fourier mp-chunks
#define CHL   208         // chunk length (5 x 208 = 1040, zero-padded past 1024)
#define TPAD  18          // padded float2 row stride for st2 (conflict-free)
#define NE    8           // synth k-slices (8 x 64 pairs = 512)

// ---- f32-faithful constants ----
#define C2PL_F   ((float)(2.0 * M_PI / 10.0))          // 2*pi/L as f32
#define FT32_F   ((float)(4.0 * 2.821e-5))             // 4*tau as f32
#define INV4T_F  (1.0f / FT32_F)                        // reciprocal (<=1ulp arg diff)
#define WIN_R    0.1090f                                // support radius (rad)
#define WJ       39                                     // window half-width in bins

// ---- scratch (device globals; no allocation allowed) ----
__device__ float  g_gsum[NB * MM];
__device__ float2 g_pF [NCH * NK * NB];  // fourier partials {C, S}
__device__ float2 g_A4 [NP4 * NJ * 2];   // [(p*32+j)*2+comp] = {Are, Aim}, k=2p+1+comp
__device__ float  g_A0 [NJ];             // k = 0 term (D*F0)
__device__ float2 g_pUV[NE * NK * NJ];   // synth partials {U, V}
__device__ float2 g_H  [NB * MM];        // H packed {c0, c1} per (b, m)
__device__ float  g_D  [2  * NK];
__device__ float2 g_cs [MM];             // {cos, sin}(2*pi*i/M)
__device__ float  g_xg [MM];

// XGRID exactly as numpy: v = i*(10/2049); xg = (2*pi*v)/10, f64 then cast f32
__device__ __forceinline__ float xgrid_f32(int m) {
    double v = (double)m * (10.0 / 2049.0);
    v = (6.283185307179586 * v) / 10.0;
    return (float)v;
}

// ============================================================================
// K_spread (init fused): gsum[b][m] = sum_n __expf(-((x_n*c - xg_m)^2)/(4tau))
// Blocks with b==0 additionally build the tables (g_cs, g_xg, g_D) for their
// tile slice; spread itself computes xg inline (no intra-launch dependence).
// ============================================================================
__global__ __launch_bounds__(128) void k_spread(
        const float* __restrict__ x,
        const float* __restrict__ sh0, const float* __restrict__ am0,
        const float* __restrict__ sh1, const float* __restrict__ am1) {
    __shared__ float cand[NPT];
    __shared__ int   warp_cnt[4];

    int b    = blockIdx.x;
    int tile = blockIdx.y;          // 0..16
    int lo   = tile * 128;
    int t    = threadIdx.x;
    int lane = t & 31, w = t >> 5;

    // ---- fused table init (one block column only) ----
    if (b == 0) {
        int i = lo + t;             // 0..2175 covers MM and NK
        if (i < MM) {
            double th = (6.283185307179586 * (double)i) / 2049.0;
            double s, c;
            sincos(th, &s, &c);
            g_cs[i] = make_float2((float)c, (float)s);
            g_xg[i] = xgrid_f32(i);
        }
        if (i < NK) {
            double tau = (double)((float)2.821e-5);
            double k2  = (double)i * (double)i;
            double dec2 = (M_PI / tau) * exp(2.0 * k2 * tau); // deconv^2
            double lo2p = 10.0 / (2.0 * M_PI);                // L/(2*pi)
            double s0 = 5.0 * (double)sh0[0];
            double s1 = 5.0 * (double)sh1[0];
            double m1 = -(double)am0[0] * 4.0 * M_PI / (k2 + s0 * s0);
            double den = k2 + s1 * s1;
            double m2 =  (double)am1[0] * 4.0 * M_PI / (den * den);
            g_D[i]      = (float)(lo2p * dec2 * m1);
            g_D[NK + i] = (float)(lo2p * dec2 * m2);
        }
    }

    // ---- phase 1: candidate compaction (deterministic n-order) ----
    const float* xb = x + b * NPT;
    float v[8];
    int flags = 0, cnt = 0;
    float fl = (float)(lo - 40), fh = (float)(lo + 127 + 40);
    #pragma unroll
    for (int i = 0; i < 8; ++i) {
        float xs = __fmul_rn(xb[i * 128 + t], C2PL_F);   // coalesced
        v[i] = xs;
        float cenf = xs * (float)(2049.0 / (2.0 * M_PI));
        int ok = (cenf >= fl) && (cenf <= fh);
        flags |= ok << i;
        cnt += ok;
    }
    int inc = cnt;
    #pragma unroll
    for (int o = 1; o < 32; o <<= 1) {
        int z = __shfl_up_sync(0xffffffffu, inc, o);
        if (lane >= o) inc += z;
    }
    if (lane == 31) warp_cnt[w] = inc;
    __syncthreads();
    int woff = 0;
    for (int i = 0; i < w; ++i) woff += warp_cnt[i];
    int ntot = warp_cnt[0] + warp_cnt[1] + warp_cnt[2] + warp_cnt[3];
    int off = woff + inc - cnt;
    #pragma unroll
    for (int i = 0; i < 8; ++i)
        if ((flags >> i) & 1) cand[off++] = v[i];
    __syncthreads();

    // ---- phase 2: one thread per bin (xg inline; table may not be ready) ----
    int m = lo + t;
    if (m < MM) {
        float xg = xgrid_f32(m);
        float acc = 0.0f;
        for (int i = 0; i < ntot; ++i) {
            float d = __fsub_rn(cand[i], xg);
            if (fabsf(d) < WIN_R) {
                float arg = __fmul_rn(__fmul_rn(d, d), INV4T_F);
                acc += __expf(-arg);
            }
        }
        g_gsum[b * MM + m] = acc;
    }
}

// ============================================================================
// K_fourier (prep fused): block stages trig (16.4KB) + computes its own
// sum/diff chunk st2 (208 x 16, stride-18 float2 rows, 16B-aligned).
// Warp = one k; lane = (par 0..7) x (slot 0..3); 26 iterations.
// ============================================================================
__global__ __launch_bounds__(256) void k_fourier() {
    __shared__ __align__(16) float2 scs[MM];           // 16392 B
    __shared__ __align__(16) float2 st2[CHL * TPAD];   // 29952 B

    int y = blockIdx.y;

    for (int i = threadIdx.x; i < MM; i += 256) scs[i] = g_cs[i];
    // fused prep: st2[mpl][b] = {g[mp]+g[M-mp], g[mp]-g[M-mp]}
    for (int e = threadIdx.x; e < CHL * NB; e += 256) {
        int b   = e / CHL;
        int mpl = e - b * CHL;
        int mp  = y * CHL + mpl;
        float2 v = make_float2(0.0f, 0.0f);
        if (mp == 0) {
            v = make_float2(g_gsum[b * MM], 0.0f);
        } else if (mp < NK) {
            float a = g_gsum[b * MM + mp];
            float c = g_gsum[b * MM + 2049 - mp];
            v = make_float2(a + c, a - c);
        }
        st2[mpl * TPAD + b] = v;
    }
    __syncthreads();

    int w    = threadIdx.x >> 5;
    int lane = threadIdx.x & 31;
    int k    = blockIdx.x * 8 + w;
    if (k >= NK) return;

    int par = lane >> 2;            // 0..7  (mp parity, stride 8)
    int s   = lane & 3;             // batch slot: batches 4s..4s+3
    int mp0 = y * CHL + par;

    int t   = (k * mp0) % MM;
    int stp = (8 * k) % MM;
    const float2* row = st2 + par * TPAD + s * 4;   // even element idx -> 16B aligned

    float c0 = 0.f, s0 = 0.f, c1 = 0.f, s1 = 0.f;
    float c2 = 0.f, s2 = 0.f, c3 = 0.f, s3 = 0.f;
    #pragma unroll
    for (int it = 0; it < 26; ++it) {       // mp0 + 8*it, 26*8 = 208 = CHL
        float2 cs = scs[t];
        const float4* p = (const float4*)(row + it * (8 * TPAD));
        float4 ga = p[0];                   // batches 4s, 4s+1
        float4 gb = p[1];                   // batches 4s+2, 4s+3
        c0 = fmaf(ga.x, cs.x, c0);
        s0 = fmaf(ga.y, cs.y, s0);
        c1 = fmaf(ga.z, cs.x, c1);
        s1 = fmaf(ga.w, cs.y, s1);
        c2 = fmaf(gb.x, cs.x, c2);
        s2 = fmaf(gb.y, cs.y, s2);
        c3 = fmaf(gb.z, cs.x, c3);
        s3 = fmaf(gb.w, cs.y, s3);
        t += stp; if (t >= MM) t -= MM;
    }
    #pragma unroll
    for (int o = 4; o <= 16; o <<= 1) {
        c0 += __shfl_xor_sync(0xffffffffu, c0, o);
        s0 += __shfl_xor_sync(0xffffffffu, s0, o);
        c1 += __shfl_xor_sync(0xffffffffu, c1, o);
        s1 += __shfl_xor_sync(0xffffffffu, s1, o);
        c2 += __shfl_xor_sync(0xffffffffu, c2, o);
        s2 += __shfl_xor_sync(0xffffffffu, s2, o);
        c3 += __shfl_xor_sync(0xffffffffu, c3, o);
        s3 += __shfl_xor_sync(0xffffffffu, s3, o);
    }
    if (lane < 4) {                 // par == 0, one lane per slot
        float4* dst = (float4*)(g_pF + (y * NK + k) * NB) + 2 * s;
        dst[0] = make_float4(c0, s0, c1, s1);
        dst[1] = make_float4(c2, s2, c3, s3);
    }
}

// ============================================================================
// K_comb: combine fourier chunk partials, fold D, write A (k-paired) + A0.
// ============================================================================
__global__ void k_comb() {
    int i = blockIdx.x * blockDim.x + threadIdx.x;
    if (i >= NK * NB) return;
    int k = i >> 4, b = i & 15;
    float C = 0.0f, S = 0.0f;
    #pragma unroll
    for (int y = 0; y < NCH; ++y) {
        float2 p = g_pF[(y * NK + k) * NB + b];
        C += p.x; S += p.y;
    }
    float re =  C;
    float im = -S;
    float D0 = g_D[k], D1 = g_D[NK + k];
    int j0 = 2 * b, j1 = 2 * b + 1;
    if (k == 0) {
        g_A0[j0] = D0 * re;
        g_A0[j1] = D1 * re;
    } else {
        int p    = (k - 1) >> 1;
        int comp = (k - 1) & 1;
        g_A4[(p * NJ + j0) * 2 + comp] = make_float2(D0 * re, D0 * im);
        g_A4[(p * NJ + j1) * 2 + comp] = make_float2(D1 * re, D1 * im);
    }
}

// ============================================================================
// K_synth: grid (65 mp-16-tiles, 8 k-slices of 64 pairs). Block stages its
// 32KB A-slab (shared by all 8 warps) into smem; warp = 2 mp, lane = j.
// ============================================================================
__global__ __launch_bounds__(256) void k_synth() {
    __shared__ __align__(16) float2 scs[MM];   // 16392 B
    __shared__ float4 sA[64 * NJ];             // 32768 B: [pair_local][j]

    int e = blockIdx.y;                     // k-slice 0..7
    int p0 = e * 64;                        // pairs p0..p0+63

    for (int i = threadIdx.x; i < MM; i += 256) scs[i] = g_cs[i];
    {
        const float4* src = (const float4*)g_A4 + p0 * NJ;
        for (int i = threadIdx.x; i < 64 * NJ; i += 256) sA[i] = src[i];
    }
    __syncthreads();

    int w    = threadIdx.x >> 5;
    int lane = threadIdx.x & 31;        // = j
    int mpA  = blockIdx.x * 16 + 2 * w;
    int mpB  = mpA + 1;
    if (mpA >= NK) return;
    bool vB = (mpB < NK);

    int k0 = 2 * p0 + 1;

    int tA  = (int)(((long long)mpA * k0) % MM);
    int tA2 = tA + mpA; if (tA2 >= MM) tA2 -= MM;
    int sAtp = (2 * mpA) % MM;
    int tB  = (int)(((long long)mpB * k0) % MM);
    int tB2 = tB + mpB; if (tB2 >= MM) tB2 -= MM;
    int sBtp = (2 * mpB) % MM;

    const float4* ap = sA + lane;

    float UA = 0.f, VA = 0.f, UB = 0.f, VB = 0.f;
    #pragma unroll 4
    for (int it = 0; it < 64; ++it) {
        float4 a = ap[it * NJ];
        float2 cA0 = scs[tA], cA1 = scs[tA2];
        UA = fmaf(a.x, cA0.x, UA);
        VA = fmaf(a.y, cA0.y, VA);
        UA = fmaf(a.z, cA1.x, UA);
        VA = fmaf(a.w, cA1.y, VA);
        if (vB) {
            float2 cB0 = scs[tB], cB1 = scs[tB2];
            UB = fmaf(a.x, cB0.x, UB);
            VB = fmaf(a.y, cB0.y, VB);
            UB = fmaf(a.z, cB1.x, UB);
            VB = fmaf(a.w, cB1.y, VB);
        }
        tA  += sAtp; if (tA  >= MM) tA  -= MM;
        tA2 += sAtp; if (tA2 >= MM) tA2 -= MM;
        tB  += sBtp; if (tB  >= MM) tB  -= MM;
        tB2 += sBtp; if (tB2 >= MM) tB2 -= MM;
    }
    g_pUV[(e * NK + mpA) * NJ + lane] = make_float2(UA, VA);
    if (vB)
        g_pUV[(e * NK + mpB) * NJ + lane] = make_float2(UB, VB);
}

// ============================================================================
// K_hcomb: combine synth partials, build packed H.
// H[mp]=(A0+2(U-V))/M, H[M-mp]=(A0+2(U+V))/M.
// ============================================================================
__global__ void k_hcomb() {
    int i = blockIdx.x * blockDim.x + threadIdx.x;
    if (i >= NK * NB) return;
    int mp = i >> 4, b = i & 15;
    int j0 = 2 * b, j1 = 2 * b + 1;
    float U0 = 0.f, V0 = 0.f, U1 = 0.f, V1 = 0.f;
    #pragma unroll
    for (int e = 0; e < NE; ++e) {
        float2 p0 = g_pUV[(e * NK + mp) * NJ + j0];
        float2 p1 = g_pUV[(e * NK + mp) * NJ + j1];
        U0 += p0.x; V0 += p0.y;
        U1 += p1.x; V1 += p1.y;
    }
    const float inv = 1.0f / 2049.0f;
    float a00 = g_A0[j0], a01 = g_A0[j1];
    float2 hm = make_float2((a00 + 2.0f * (U0 - V0)) * inv,
                            (a01 + 2.0f * (U1 - V1)) * inv);
    g_H[b * MM + mp] = hm;
    if (mp) {
        float2 hp = make_float2((a00 + 2.0f * (U0 + V0)) * inv,
                                (a01 + 2.0f * (U1 + V1)) * inv);
        g_H[b * MM + 2049 - mp] = hp;
    }
}

// ============================================================================
// K_out: fmm[b,n,c] = (1/M) * sum_{m in window} g[b,n,m] * H[b][m].c
// Pure f32 (reference itself sums in f32; 79-term window sum is better-
// conditioned than the reference's 2049-term sum).
// ============================================================================
__global__ __launch_bounds__(256) void k_out(const float* __restrict__ x,
                                             float* __restrict__ out) {
    int gid = blockIdx.x * blockDim.x + threadIdx.x;
    if (gid >= NB * NPT) return;
    int b = gid / NPT;

    float xs = __fmul_rn(x[gid], C2PL_F);
    int cen = __float2int_rn(xs * (float)(2049.0 / (2.0 * M_PI)));

    const float2* Hb = g_H + b * MM;

    float a0 = 0.0f, a1 = 0.0f;
    #pragma unroll 4
    for (int j = -WJ; j <= WJ; ++j) {
        int m = cen + j;
        if (m < 0 || m >= MM) continue;
        float d = __fsub_rn(xs, g_xg[m]);
        if (fabsf(d) < WIN_R) {
            float arg = __fmul_rn(__fmul_rn(d, d), INV4T_F);
            float gv = __expf(-arg);
            float2 h = Hb[m];
            a0 = fmaf(gv, h.x, a0);
            a1 = fmaf(gv, h.y, a1);
        }
    }
    const float inv = 1.0f / 2049.0f;
    out[gid * 2 + 0] = a0 * inv;
    out[gid * 2 + 1] = a1 * inv;
}

// ============================================================================
extern "C" void kernel_launch(void* const* d_in, const int* in_sizes, int n_in,
                              void* d_out, int out_size) {
    const float* x   = (const float*)d_in[0];
    const float* sh0 = (const float*)d_in[1];
    const float* am0 = (const float*)d_in[2];
    const float* sh1 = (const float*)d_in[3];
    const float* am1 = (const float*)d_in[4];
    float* out = (float*)d_out;

    dim3 gsp(NB, 17);
    k_spread<<<gsp, 128>>>(x, sh0, am0, sh1, am1);   // init fused (b==0 blocks)

    dim3 gf(129, NCH);                  // 8 k per block x 5 mp-chunks (prep fused)
    k_fourier<<<gf, 256>>>();
    k_comb<<<(NK * NB + 255) / 256, 256>>>();

    dim3 gsy(65, NE);                   // 16 mp per block x 8 k-slices
    k_synth<<<gsy, 256>>>();
    k_hcomb<<<(NK * NB + 255) / 256, 256>>>();

    k_out<<<(NB * NPT + 255) / 256, 256>>>(x, out);
}